// round 3
// baseline (speedup 1.0000x reference)
#include <cuda_runtime.h>
#include <cuda_bf16.h>
#include <math.h>
#include <stdint.h>

#define BB 8
#define SS 4096
#define HH 768
#define MS 64
#define F1 4096
#define F2 256
#define SEPTOK 2
#define MROWS 512          // BB*MS
#define K1P (3*HH)         // 2304 : [hi | lo | hi] along K for GEMM1
#define K2P (3*F1)         // 12288: [hi | lo | hi] along K for GEMM2
#define NSPLIT 16

// tcgen05 is only legal on arch-specific / family compile passes. The base
// compute_103 PTX pass must not see any tcgen05 asm (ptxas rejects it).
#if defined(__CUDA_ARCH_FEAT_SM103_ALL) || defined(__CUDA_ARCH_FEAT_SM100_ALL) || \
    defined(__CUDA_ARCH_FEAT_SM101_ALL) || defined(__CUDA_ARCH_SPECIFIC__) ||     \
    defined(__CUDA_ARCH_FAMILY_SPECIFIC__)
#define HAS_TCGEN05 1
#else
#define HAS_TCGEN05 0
#endif

// ---------------- scratch (device globals; no allocation allowed) ----------
__device__ __nv_bfloat16 g_sentb[MROWS * K1P];   // A' for GEMM1 (hi|lo|hi)
__device__ __nv_bfloat16 g_w1b[F1 * K1P];        // B' for GEMM1 (W1^T: hi|hi|lo)
__device__ __nv_bfloat16 g_x1b[MROWS * K2P];     // A' for GEMM2 (hi|lo|hi)
__device__ __nv_bfloat16 g_w2b[F2 * K2P];        // B' for GEMM2 (W2^T: hi|hi|lo)
__device__ float g_x2p[NSPLIT * MROWS * F2];     // split-K partials
__device__ float g_x2[MROWS * F2];
__device__ int   g_sep_pos[BB][SS];
__device__ int   g_nsep[BB];

__device__ __forceinline__ float gelu_exact(float x) {
    return 0.5f * x * (1.0f + erff(x * 0.70710678118654752f));
}

// ---------------- PTX helpers (used only under HAS_TCGEN05) ----------------
__device__ __forceinline__ uint32_t smem_u32(const void* p) {
    uint32_t a;
    asm("{ .reg .u64 t; cvta.to.shared.u64 t, %1; cvt.u32.u64 %0, t; }" : "=r"(a) : "l"(p));
    return a;
}

#if HAS_TCGEN05
__device__ __forceinline__ uint32_t elect1() {
    uint32_t p;
    asm volatile("{ .reg .pred p; elect.sync _|p, 0xFFFFFFFF; selp.b32 %0,1,0,p; }" : "=r"(p));
    return p;
}
__device__ __forceinline__ void mma_f16_ss_cg1(uint32_t d, uint64_t ad, uint64_t bd,
                                               uint32_t idesc, bool en) {
    uint32_t e = en ? 1u : 0u;
    asm volatile(
        "{\n\t.reg .pred p;\n\t"
        "setp.ne.u32 p, %5, 0;\n\t"
        "tcgen05.mma.cta_group::1.kind::f16 [%0], %1, %2, %3, {%4, %4, %4, %4}, p;\n\t}"
        :: "r"(d), "l"(ad), "l"(bd), "r"(idesc), "r"(0u), "r"(e) : "memory");
}

#define MBAR_INIT(a, c) \
    asm volatile("mbarrier.init.shared.b64 [%0], %1;" :: "r"(a), "r"(c) : "memory")
#define MBAR_WAIT(mb, par) do {                                                        \
    uint32_t _m = (mb), _p = (par), _d;                                                \
    asm volatile("{\n\t.reg .pred p;\n\t"                                              \
        "mbarrier.try_wait.parity.acquire.cta.shared::cta.b64 p, [%1], %2;\n\t"        \
        "selp.b32 %0, 1, 0, p;\n\t}" : "=r"(_d) : "r"(_m), "r"(_p) : "memory");        \
    if (!_d) {                                                                         \
        asm volatile("{\n\t.reg .pred P1;\n\t"                                         \
            "WAIT_LOOP_%=:\n\t"                                                        \
            "mbarrier.try_wait.parity.acquire.cta.shared::cta.b64 P1, [%0], %1, 0x989680;\n\t" \
            "@P1 bra.uni WAIT_DONE_%=;\n\t"                                            \
            "bra.uni WAIT_LOOP_%=;\n\t"                                                \
            "WAIT_DONE_%=:\n\t}" :: "r"(_m), "r"(_p) : "memory");                      \
    }                                                                                  \
} while (0)

#define LDTM_X32(r, addr)                                                             \
    asm volatile("tcgen05.ld.sync.aligned.32x32b.x32.b32 "                            \
        "{%0, %1, %2, %3, %4, %5, %6, %7, "                                           \
        " %8, %9, %10, %11, %12, %13, %14, %15, "                                     \
        " %16, %17, %18, %19, %20, %21, %22, %23, "                                   \
        " %24, %25, %26, %27, %28, %29, %30, %31}, [%32];"                            \
        : "=r"((r)[0]),  "=r"((r)[1]),  "=r"((r)[2]),  "=r"((r)[3]),                  \
          "=r"((r)[4]),  "=r"((r)[5]),  "=r"((r)[6]),  "=r"((r)[7]),                  \
          "=r"((r)[8]),  "=r"((r)[9]),  "=r"((r)[10]), "=r"((r)[11]),                 \
          "=r"((r)[12]), "=r"((r)[13]), "=r"((r)[14]), "=r"((r)[15]),                 \
          "=r"((r)[16]), "=r"((r)[17]), "=r"((r)[18]), "=r"((r)[19]),                 \
          "=r"((r)[20]), "=r"((r)[21]), "=r"((r)[22]), "=r"((r)[23]),                 \
          "=r"((r)[24]), "=r"((r)[25]), "=r"((r)[26]), "=r"((r)[27]),                 \
          "=r"((r)[28]), "=r"((r)[29]), "=r"((r)[30]), "=r"((r)[31])                  \
        : "r"(addr))

static constexpr uint64_t DESC_BASE_SW128 =
    (uint64_t(2) << 61) | (uint64_t(1) << 46) | (uint64_t(64) << 32) | (uint64_t(1) << 16);
__device__ __forceinline__ uint64_t make_desc(uint32_t addr) {
    return DESC_BASE_SW128 | ((uint64_t)(addr >> 4) & 0x3FFF);
}
__device__ __forceinline__ uint32_t sw128(uint32_t off) {
    return off ^ ((off >> 3) & 0x70);
}
#endif  // HAS_TCGEN05

// ---------------- 1) sep scan ----------------------------------------------
__global__ void sep_scan_kernel(const int* __restrict__ ids32) {
    const int b = blockIdx.x;
    const int tid = threadIdx.x;
    const int stride = (ids32[1] == 0) ? 2 : 1;   // int64 vs int32 auto-detect
    const int* row = ids32 + (size_t)b * SS * stride;

    __shared__ int cnt[256];
    __shared__ int excl[257];

    const int base = tid * 16;
    int c = 0;
    #pragma unroll
    for (int i = 0; i < 16; i++)
        if (row[(base + i) * stride] == SEPTOK) c++;
    cnt[tid] = c;
    __syncthreads();

    if (tid == 0) {
        int acc = 0;
        for (int i = 0; i < 256; i++) { excl[i] = acc; acc += cnt[i]; }
        excl[256] = acc;
        g_nsep[b] = acc;
    }
    __syncthreads();

    int off = excl[tid];
    for (int i = 0; i < 16; i++)
        if (row[(base + i) * stride] == SEPTOK)
            g_sep_pos[b][off++] = base + i;
}

// ---------------- 2) pooling; emits bf16 hi/lo A' for GEMM1 ----------------
__global__ void pool_kernel(const float* __restrict__ hidden) {
    const int s   = blockIdx.x;   // 0..63
    const int b   = blockIdx.y;   // 0..7
    const int tid = threadIdx.x;  // 256
    const int n   = g_nsep[b];

    int t0 = 0, t1 = 0;
    if (n == 0) {
        if (s == 0) { t0 = 0; t1 = SS; }
    } else if (s < n) {
        if (s == 0) { t0 = 0; t1 = g_sep_pos[b][0] + 1; }
        else        { t0 = g_sep_pos[b][s - 1] + 1; t1 = g_sep_pos[b][s]; }
    } else if (s == n) {
        t0 = g_sep_pos[b][n - 1] + 1; t1 = SS - 1;
    }

    float a0 = 0.f, a1 = 0.f, a2 = 0.f;
    const float* hb = hidden + (size_t)b * SS * HH;
    #pragma unroll 4
    for (int t = t0; t < t1; t++) {
        const float* p = hb + (size_t)t * HH + tid;
        a0 += p[0]; a1 += p[256]; a2 += p[512];
    }
    const int cnt = t1 - t0;
    const float inv = (cnt > 0) ? (1.0f / (float)cnt) : 0.0f;

    float vals[3] = {a0 * inv, a1 * inv, a2 * inv};
    const size_t rb = (size_t)(b * MS + s) * K1P;
    #pragma unroll
    for (int j = 0; j < 3; j++) {
        int d = tid + j * 256;
        float v = vals[j];
        __nv_bfloat16 h = __float2bfloat16(v);
        __nv_bfloat16 l = __float2bfloat16(v - __bfloat162float(h));
        g_sentb[rb + d]          = h;   // chunk 0: hi
        g_sentb[rb + HH + d]     = l;   // chunk 1: lo
        g_sentb[rb + 2 * HH + d] = h;   // chunk 2: hi
    }
}

// ---------------- 3) weight transpose + hi/lo split ------------------------
// W: [K, N] row-major  ->  out: [N, 3K] bf16 with [hi | hi | lo]
__global__ void conv_w_kernel(const float* __restrict__ W, __nv_bfloat16* __restrict__ out,
                              int K, int N) {
    __shared__ float t[32][33];
    const int n0 = blockIdx.x * 32, k0 = blockIdx.y * 32;
    const int tx = threadIdx.x, ty = threadIdx.y;   // 32 x 8
    #pragma unroll
    for (int i = 0; i < 4; i++)
        t[ty + i * 8][tx] = W[(size_t)(k0 + ty + i * 8) * N + n0 + tx];
    __syncthreads();
    #pragma unroll
    for (int i = 0; i < 4; i++) {
        const int nn = n0 + ty + i * 8;
        const float v = t[tx][ty + i * 8];            // = W[k0+tx][nn]
        __nv_bfloat16 h = __float2bfloat16(v);
        __nv_bfloat16 l = __float2bfloat16(v - __bfloat162float(h));
        const size_t base = (size_t)nn * (3 * (size_t)K) + k0 + tx;
        out[base]         = h;   // chunk 0: hi
        out[base + K]     = h;   // chunk 1: hi (pairs with A-lo)
        out[base + 2 * K] = l;   // chunk 2: lo (pairs with A-hi)
    }
}

// ---------------- 4) bf16 GEMM, 128x128 tile -------------------------------
// EPI==1: D + bias -> GELU -> write bf16 hi/lo A' for GEMM2 into OutB
// EPI==0: split-K partial fp32 into Cout[z]
// sm_103a pass: tcgen05 pipeline. Base pass: smem-tiled FFMA fallback
// (same semantics; only used if the runtime ever JITs base PTX).
template<int EPI>
__global__ __launch_bounds__(128)
void mma_gemm(const __nv_bfloat16* __restrict__ A, int lda,
              const __nv_bfloat16* __restrict__ Bm, int ldb,
              int nStages,
              const float* __restrict__ bias,
              float* __restrict__ Cout,
              __nv_bfloat16* __restrict__ OutB)
{
    extern __shared__ char dsm_raw[];
    char* dsm = (char*)(((uintptr_t)dsm_raw + 1023) & ~(uintptr_t)1023);  // 1KB align

    const int tid  = threadIdx.x;
    const int m0   = blockIdx.y * 128;
    const int n0   = blockIdx.x * 128;
    const int z    = blockIdx.z;
    const int ks0  = z * nStages * 64;

#if HAS_TCGEN05
    __shared__ uint32_t s_tmem[1];
    __shared__ __align__(8) uint64_t s_mbar[2];

    const int wid  = tid >> 5, lane = tid & 31;
    const uint32_t smA     = smem_u32(dsm);
    const uint32_t tmem_pa = smem_u32(&s_tmem[0]);
    const uint32_t mbar_a  = smem_u32(&s_mbar[0]);

    if (wid == 0) {
        asm volatile("tcgen05.alloc.cta_group::1.sync.aligned.shared::cta.b32 [%0], %1;"
                     :: "r"(tmem_pa), "r"(128u) : "memory");
        asm volatile("tcgen05.relinquish_alloc_permit.cta_group::1.sync.aligned;");
        if (tid == 0) { MBAR_INIT(mbar_a, 1); MBAR_INIT(mbar_a + 8, 1); }
    }
    __syncthreads();
    const uint32_t tmem = s_tmem[0];

    const uint32_t IDESC = (1u << 4) | (1u << 7) | (1u << 10) |
                           ((128u / 8) << 17) | ((128u / 16) << 24);

    auto load_stage = [&](int buf, int s) {
        const int ko = ks0 + s * 64;
        const __nv_bfloat16* Ag = A  + (size_t)m0 * lda + ko;
        const __nv_bfloat16* Bg = Bm + (size_t)n0 * ldb + ko;
        char* dA = dsm + buf * 16384;
        char* dB = dsm + 32768 + buf * 16384;
        #pragma unroll
        for (int i = 0; i < 8; i++) {
            const int ch = tid + i * 128;        // 1024 16B chunks per tile
            const int r = ch >> 3, c = ch & 7;
            const uint32_t sw = sw128((uint32_t)(r * 128 + c * 16));
            *(uint4*)(dA + sw) = *(const uint4*)(Ag + (size_t)r * lda + c * 8);
            *(uint4*)(dB + sw) = *(const uint4*)(Bg + (size_t)r * ldb + c * 8);
        }
    };

    load_stage(0, 0);
    for (int s = 0; s < nStages; s++) {
        __syncthreads();                              // stage-s smem visible
        if (wid == 0 && elect1()) {
            asm volatile("fence.proxy.async.shared::cta;" ::: "memory");
            const uint32_t bufA = smA + (s & 1) * 16384;
            const uint32_t bufB = smA + 32768 + (s & 1) * 16384;
            const uint64_t ad = make_desc(bufA);
            const uint64_t bd = make_desc(bufB);
            #pragma unroll
            for (int sub = 0; sub < 4; sub++)         // 4 x K=16 within the 64-wide stage
                mma_f16_ss_cg1(tmem, ad + sub * 2, bd + sub * 2, IDESC, (s > 0) || (sub > 0));
            asm volatile(
                "tcgen05.commit.cta_group::1.mbarrier::arrive::one.shared::cluster.b64 [%0];"
                :: "r"(mbar_a + (uint32_t)((s & 1) * 8)) : "memory");
        }
        if (s + 1 < nStages) {
            if (s >= 1)                               // stage s-1 (same buf as s+1) done?
                MBAR_WAIT(mbar_a + ((s + 1) & 1) * 8, ((s - 1) >> 1) & 1);
            load_stage((s + 1) & 1, s + 1);
        }
    }
    MBAR_WAIT(mbar_a + ((nStages - 1) & 1) * 8, ((nStages - 1) >> 1) & 1);
    asm volatile("tcgen05.fence::after_thread_sync;" ::: "memory");

    // ---- epilogue: warp w owns rows w*32..w*32+31 (its TMEM subpartition)
    const int m = wid * 32 + lane;
    if (EPI == 1) {
        const size_t rowbase = (size_t)(m0 + m) * K2P;
        for (int c0 = 0; c0 < 128; c0 += 32) {
            uint32_t r[32];
            LDTM_X32(r, tmem + c0);
            asm volatile("tcgen05.wait::ld.sync.aligned;" ::: "memory");
            #pragma unroll
            for (int j = 0; j < 32; j += 2) {
                const int f = n0 + c0 + j;
                float v0 = gelu_exact(__uint_as_float(r[j])     + __ldg(&bias[f]));
                float v1 = gelu_exact(__uint_as_float(r[j + 1]) + __ldg(&bias[f + 1]));
                __nv_bfloat16 h0 = __float2bfloat16(v0);
                __nv_bfloat16 h1 = __float2bfloat16(v1);
                __nv_bfloat16 l0 = __float2bfloat16(v0 - __bfloat162float(h0));
                __nv_bfloat16 l1 = __float2bfloat16(v1 - __bfloat162float(h1));
                __nv_bfloat162 hh; hh.x = h0; hh.y = h1;
                __nv_bfloat162 ll; ll.x = l0; ll.y = l1;
                *(__nv_bfloat162*)(&OutB[rowbase + f])           = hh;  // hi
                *(__nv_bfloat162*)(&OutB[rowbase + F1 + f])      = ll;  // lo
                *(__nv_bfloat162*)(&OutB[rowbase + 2 * F1 + f])  = hh;  // hi
            }
        }
    } else {
        float* Cp = Cout + (size_t)z * MROWS * F2 + (size_t)(m0 + m) * F2 + n0;
        for (int c0 = 0; c0 < 128; c0 += 32) {
            uint32_t r[32];
            LDTM_X32(r, tmem + c0);
            asm volatile("tcgen05.wait::ld.sync.aligned;" ::: "memory");
            #pragma unroll
            for (int j = 0; j < 32; j += 4) {
                float4 v;
                v.x = __uint_as_float(r[j]);     v.y = __uint_as_float(r[j + 1]);
                v.z = __uint_as_float(r[j + 2]); v.w = __uint_as_float(r[j + 3]);
                *(float4*)(Cp + c0 + j) = v;
            }
        }
    }

    __syncthreads();
    if (wid == 0)
        asm volatile("tcgen05.dealloc.cta_group::1.sync.aligned.b32 %0, %1;"
                     :: "r"(tmem), "r"(128u));

#else  // ---------------- base-arch FFMA fallback --------------------------
    float* As = (float*)dsm;                      // [32][132]
    float* Bs = (float*)(dsm + 32 * 132 * 4);     // [32][36]
    const int tyF = tid >> 3;                     // 0..15 -> rows tyF*8..+8
    const int txF = tid & 7;                      // 0..7  -> 4 cols in chunk
    const int Ktot = nStages * 64;

    for (int nc = 0; nc < 128; nc += 32) {
        float acc[8][4];
        #pragma unroll
        for (int i = 0; i < 8; i++)
            #pragma unroll
            for (int j = 0; j < 4; j++) acc[i][j] = 0.f;

        for (int k0 = 0; k0 < Ktot; k0 += 32) {
            __syncthreads();
            #pragma unroll
            for (int i = 0; i < 32; i++) {
                const int idx = tid * 32 + i;     // 4096 A elems
                const int mm = idx >> 5, kk = idx & 31;
                As[kk * 132 + mm] =
                    __bfloat162float(A[(size_t)(m0 + mm) * lda + ks0 + k0 + kk]);
            }
            #pragma unroll
            for (int i = 0; i < 8; i++) {
                const int idx = tid * 8 + i;      // 1024 B elems
                const int nn = idx >> 5, kk = idx & 31;
                Bs[kk * 36 + nn] =
                    __bfloat162float(Bm[(size_t)(n0 + nc + nn) * ldb + ks0 + k0 + kk]);
            }
            __syncthreads();
            for (int kk = 0; kk < 32; kk++)
                #pragma unroll
                for (int i = 0; i < 8; i++)
                    #pragma unroll
                    for (int j = 0; j < 4; j++)
                        acc[i][j] = fmaf(As[kk * 132 + tyF * 8 + i],
                                         Bs[kk * 36 + txF * 4 + j], acc[i][j]);
        }

        #pragma unroll
        for (int i = 0; i < 8; i++) {
            const int m = m0 + tyF * 8 + i;
            #pragma unroll
            for (int j = 0; j < 4; j++) {
                const int f = n0 + nc + txF * 4 + j;
                if (EPI == 1) {
                    float v = gelu_exact(acc[i][j] + bias[f]);
                    __nv_bfloat16 h = __float2bfloat16(v);
                    __nv_bfloat16 l = __float2bfloat16(v - __bfloat162float(h));
                    const size_t rowbase = (size_t)m * K2P;
                    OutB[rowbase + f]          = h;
                    OutB[rowbase + F1 + f]     = l;
                    OutB[rowbase + 2 * F1 + f] = h;
                } else {
                    Cout[(size_t)z * MROWS * F2 + (size_t)m * F2 + f] = acc[i][j];
                }
            }
        }
    }
#endif
}

// ---------------- 5) split-K reduce + bias + GELU --------------------------
__global__ void reduce_gelu_kernel(const float* __restrict__ b2) {
    const int idx = blockIdx.x * blockDim.x + threadIdx.x;
    float s = 0.f;
    #pragma unroll
    for (int i = 0; i < NSPLIT; i++) s += g_x2p[(size_t)i * MROWS * F2 + idx];
    g_x2[idx] = gelu_exact(s + b2[idx & (F2 - 1)]);
}

// ---------------- 6) head GEMM: [512,256]@[256,2] + b3 ---------------------
__global__ void head_kernel(const float* __restrict__ W3,
                            const float* __restrict__ b3,
                            float* __restrict__ out) {
    const int row = blockIdx.x;
    const int tid = threadIdx.x;
    const float x = g_x2[(size_t)row * F2 + tid];
    __shared__ float sh0[256];
    __shared__ float sh1[256];
    sh0[tid] = x * W3[tid * 2 + 0];
    sh1[tid] = x * W3[tid * 2 + 1];
    __syncthreads();
    for (int o = 128; o > 0; o >>= 1) {
        if (tid < o) { sh0[tid] += sh0[tid + o]; sh1[tid] += sh1[tid + o]; }
        __syncthreads();
    }
    if (tid == 0) {
        out[row * 2 + 0] = sh0[0] + b3[0];
        out[row * 2 + 1] = sh1[0] + b3[1];
    }
}

// ---------------- launch ----------------------------------------------------
extern "C" void kernel_launch(void* const* d_in, const int* in_sizes, int n_in,
                              void* d_out, int out_size) {
    const float* hidden = (const float*)d_in[0];
    const int*   ids32  = (const int*)  d_in[1];
    const float* W1 = (const float*)d_in[2];
    const float* b1 = (const float*)d_in[3];
    const float* W2 = (const float*)d_in[4];
    const float* b2 = (const float*)d_in[5];
    const float* W3 = (const float*)d_in[6];
    const float* b3 = (const float*)d_in[7];
    float* out = (float*)d_out;

    void *p_sentb, *p_w1b, *p_x1b, *p_w2b, *p_x2p;
    cudaGetSymbolAddress(&p_sentb, g_sentb);
    cudaGetSymbolAddress(&p_w1b,   g_w1b);
    cudaGetSymbolAddress(&p_x1b,   g_x1b);
    cudaGetSymbolAddress(&p_w2b,   g_w2b);
    cudaGetSymbolAddress(&p_x2p,   g_x2p);

    const int SMEM_DYN = 66560;   // 64KB tiles + 1KB align slack
    cudaFuncSetAttribute(mma_gemm<1>, cudaFuncAttributeMaxDynamicSharedMemorySize, SMEM_DYN);
    cudaFuncSetAttribute(mma_gemm<0>, cudaFuncAttributeMaxDynamicSharedMemorySize, SMEM_DYN);

    sep_scan_kernel<<<BB, 256>>>(ids32);
    pool_kernel<<<dim3(MS, BB), 256>>>(hidden);

    conv_w_kernel<<<dim3(F1 / 32, HH / 32), dim3(32, 8)>>>(W1, (__nv_bfloat16*)p_w1b, HH, F1);
    conv_w_kernel<<<dim3(F2 / 32, F1 / 32), dim3(32, 8)>>>(W2, (__nv_bfloat16*)p_w2b, F1, F2);

    // GEMM1: [512, 2304'] x [4096, 2304'] -> gelu -> bf16 hi/lo x1
    mma_gemm<1><<<dim3(F1 / 128, MROWS / 128, 1), 128, SMEM_DYN>>>(
        (const __nv_bfloat16*)p_sentb, K1P, (const __nv_bfloat16*)p_w1b, K1P,
        K1P / 64, b1, nullptr, (__nv_bfloat16*)p_x1b);

    // GEMM2: [512, 12288'] x [256, 12288'], split-K=16 -> fp32 partials
    mma_gemm<0><<<dim3(F2 / 128, MROWS / 128, NSPLIT), 128, SMEM_DYN>>>(
        (const __nv_bfloat16*)p_x1b, K2P, (const __nv_bfloat16*)p_w2b, K2P,
        K2P / (64 * NSPLIT), nullptr, (float*)p_x2p, nullptr);

    reduce_gelu_kernel<<<(MROWS * F2) / 256, 256>>>(b2);
    head_kernel<<<MROWS, 256>>>(W3, b3, out);
}

// round 5
// speedup vs baseline: 3.0156x; 3.0156x over previous
#include <cuda_runtime.h>
#include <cuda_bf16.h>
#include <math.h>
#include <stdint.h>

#define BB 8
#define SS 4096
#define HH 768
#define MS 64
#define F1 4096
#define F2 256
#define SEPTOK 2
#define MROWS 512          // BB*MS
#define K1P (3*HH)         // 2304 : [hi | lo | hi] along K for GEMM1
#define K2P (3*F1)         // 12288: [hi | lo | hi] along K for GEMM2
#define NSPLIT 16

// ---------------- scratch (device globals; no allocation allowed) ----------
// NOTE: 1024B alignment is load-bearing: cp.async.cg 16B requires 16B-aligned
// global addresses; float2/uint4 epilogue stores require 8/16B. Natural
// alignment of a bf16 array is only 2B.
__device__ __align__(1024) __nv_bfloat16 g_sentb[MROWS * K1P];   // A' GEMM1 (hi|lo|hi)
__device__ __align__(1024) __nv_bfloat16 g_w1b[F1 * K1P];        // B' GEMM1 (W1^T: hi|hi|lo)
__device__ __align__(1024) __nv_bfloat16 g_x1b[MROWS * K2P];     // A' GEMM2 (hi|lo|hi)
__device__ __align__(1024) __nv_bfloat16 g_w2b[F2 * K2P];        // B' GEMM2 (W2^T: hi|hi|lo)
__device__ __align__(1024) float g_x2p[NSPLIT * MROWS * F2];     // split-K partials
__device__ __align__(1024) float g_x2[MROWS * F2];
__device__ int   g_sep_pos[BB][SS];
__device__ int   g_nsep[BB];

__device__ __forceinline__ float gelu_exact(float x) {
    return 0.5f * x * (1.0f + erff(x * 0.70710678118654752f));
}

__device__ __forceinline__ uint32_t smem_u32(const void* p) {
    uint32_t a;
    asm("{ .reg .u64 t; cvta.to.shared.u64 t, %1; cvt.u32.u64 %0, t; }" : "=r"(a) : "l"(p));
    return a;
}
__device__ __forceinline__ uint32_t sw128(uint32_t off) {
    return off ^ ((off >> 3) & 0x70);
}
__device__ __forceinline__ void cp_async16(uint32_t dst, const void* src) {
    asm volatile("cp.async.cg.shared.global [%0], [%1], 16;" :: "r"(dst), "l"(src) : "memory");
}
__device__ __forceinline__ void cp_commit() {
    asm volatile("cp.async.commit_group;" ::: "memory");
}
template<int N>
__device__ __forceinline__ void cp_waitg() {
    asm volatile("cp.async.wait_group %0;" :: "n"(N) : "memory");
}
__device__ __forceinline__ void ldsm_x4(uint32_t* r, uint32_t addr) {
    asm volatile("ldmatrix.sync.aligned.m8n8.x4.shared.b16 {%0,%1,%2,%3}, [%4];"
                 : "=r"(r[0]), "=r"(r[1]), "=r"(r[2]), "=r"(r[3]) : "r"(addr));
}
__device__ __forceinline__ void mma16816(float* d, const uint32_t* a, const uint32_t* b) {
    asm volatile(
        "mma.sync.aligned.m16n8k16.row.col.f32.bf16.bf16.f32 "
        "{%0,%1,%2,%3}, {%4,%5,%6,%7}, {%8,%9}, {%0,%1,%2,%3};"
        : "+f"(d[0]), "+f"(d[1]), "+f"(d[2]), "+f"(d[3])
        : "r"(a[0]), "r"(a[1]), "r"(a[2]), "r"(a[3]), "r"(b[0]), "r"(b[1]));
}

// ---------------- 1) sep scan ----------------------------------------------
__global__ void sep_scan_kernel(const int* __restrict__ ids32) {
    const int b = blockIdx.x;
    const int tid = threadIdx.x;
    const int stride = (ids32[1] == 0) ? 2 : 1;   // int64 vs int32 auto-detect
    const int* row = ids32 + (size_t)b * SS * stride;

    __shared__ int cnt[256];
    __shared__ int excl[257];

    const int base = tid * 16;
    int c = 0;
    #pragma unroll
    for (int i = 0; i < 16; i++)
        if (row[(base + i) * stride] == SEPTOK) c++;
    cnt[tid] = c;
    __syncthreads();

    if (tid == 0) {
        int acc = 0;
        for (int i = 0; i < 256; i++) { excl[i] = acc; acc += cnt[i]; }
        excl[256] = acc;
        g_nsep[b] = acc;
    }
    __syncthreads();

    int off = excl[tid];
    for (int i = 0; i < 16; i++)
        if (row[(base + i) * stride] == SEPTOK)
            g_sep_pos[b][off++] = base + i;
}

// ---------------- 2) pooling; emits bf16 hi/lo A' for GEMM1 ----------------
__global__ void pool_kernel(const float* __restrict__ hidden) {
    const int s   = blockIdx.x;   // 0..63
    const int b   = blockIdx.y;   // 0..7
    const int tid = threadIdx.x;  // 256
    const int n   = g_nsep[b];

    int t0 = 0, t1 = 0;
    if (n == 0) {
        if (s == 0) { t0 = 0; t1 = SS; }
    } else if (s < n) {
        if (s == 0) { t0 = 0; t1 = g_sep_pos[b][0] + 1; }
        else        { t0 = g_sep_pos[b][s - 1] + 1; t1 = g_sep_pos[b][s]; }
    } else if (s == n) {
        t0 = g_sep_pos[b][n - 1] + 1; t1 = SS - 1;
    }

    float a0 = 0.f, a1 = 0.f, a2 = 0.f;
    const float* hb = hidden + (size_t)b * SS * HH;
    #pragma unroll 4
    for (int t = t0; t < t1; t++) {
        const float* p = hb + (size_t)t * HH + tid;
        a0 += p[0]; a1 += p[256]; a2 += p[512];
    }
    const int cnt = t1 - t0;
    const float inv = (cnt > 0) ? (1.0f / (float)cnt) : 0.0f;

    float vals[3] = {a0 * inv, a1 * inv, a2 * inv};
    const size_t rb = (size_t)(b * MS + s) * K1P;
    #pragma unroll
    for (int j = 0; j < 3; j++) {
        int d = tid + j * 256;
        float v = vals[j];
        __nv_bfloat16 h = __float2bfloat16(v);
        __nv_bfloat16 l = __float2bfloat16(v - __bfloat162float(h));
        g_sentb[rb + d]          = h;   // chunk 0: hi
        g_sentb[rb + HH + d]     = l;   // chunk 1: lo
        g_sentb[rb + 2 * HH + d] = h;   // chunk 2: hi
    }
}

// ---------------- 3) weight transpose + hi/lo split ------------------------
// W: [K, N] row-major  ->  out: [N, 3K] bf16 with [hi | hi | lo]
__global__ void conv_w_kernel(const float* __restrict__ W, __nv_bfloat16* __restrict__ out,
                              int K, int N) {
    __shared__ float t[32][33];
    const int n0 = blockIdx.x * 32, k0 = blockIdx.y * 32;
    const int tx = threadIdx.x, ty = threadIdx.y;   // 32 x 8
    #pragma unroll
    for (int i = 0; i < 4; i++)
        t[ty + i * 8][tx] = W[(size_t)(k0 + ty + i * 8) * N + n0 + tx];
    __syncthreads();
    #pragma unroll
    for (int i = 0; i < 4; i++) {
        const int nn = n0 + ty + i * 8;
        const float v = t[tx][ty + i * 8];            // = W[k0+tx][nn]
        __nv_bfloat16 h = __float2bfloat16(v);
        __nv_bfloat16 l = __float2bfloat16(v - __bfloat162float(h));
        const size_t base = (size_t)nn * (3 * (size_t)K) + k0 + tx;
        out[base]         = h;   // chunk 0: hi
        out[base + K]     = h;   // chunk 1: hi (pairs with A-lo)
        out[base + 2 * K] = l;   // chunk 2: lo (pairs with A-hi)
    }
}

// ---------------- 4) mma.sync bf16 GEMM, 128x128 tile, K staged 64 ---------
// Base-PTX-legal tensor path (HMMA). A: [M, lda] K-major bf16. B: [N, ldb]
// K-major bf16 (i.e. B^T). cp.async double-buffered SW128 smem tiles;
// ldmatrix fragments; 8 warps in a 4(m) x 2(n) grid, warp tile 32x64.
// EPI==1: D + bias -> GELU -> write bf16 hi/lo A' for GEMM2 into OutB
// EPI==0: split-K partial fp32 into Cout[z]
template<int EPI>
__global__ __launch_bounds__(256)
void mma_gemm(const __nv_bfloat16* __restrict__ A, int lda,
              const __nv_bfloat16* __restrict__ Bm, int ldb,
              int nStages,
              const float* __restrict__ bias,
              float* __restrict__ Cout,
              __nv_bfloat16* __restrict__ OutB)
{
    extern __shared__ char dsm_raw[];
    char* dsm = (char*)(((uintptr_t)dsm_raw + 1023) & ~(uintptr_t)1023);  // 1KB align

    const int tid  = threadIdx.x;
    const int wid  = tid >> 5, lane = tid & 31;
    const int m0   = blockIdx.y * 128;
    const int n0   = blockIdx.x * 128;
    const int z    = blockIdx.z;
    const int ks0  = z * nStages * 64;

    const uint32_t smBase = smem_u32(dsm);

    // ---- async stage loader: 32KB per stage (A 16KB + B 16KB)
    auto load_stage = [&](int buf, int s) {
        const int ko = ks0 + s * 64;
        const __nv_bfloat16* Ag = A  + (size_t)m0 * lda + ko;
        const __nv_bfloat16* Bg = Bm + (size_t)n0 * ldb + ko;
        const uint32_t dA = smBase + buf * 16384;
        const uint32_t dB = smBase + 32768 + buf * 16384;
        #pragma unroll
        for (int i = 0; i < 4; i++) {
            const int ch = tid + i * 256;           // 1024 16B chunks per tile
            const int r = ch >> 3, c = ch & 7;
            const uint32_t sw = sw128((uint32_t)(r * 128 + c * 16));
            cp_async16(dA + sw, Ag + (size_t)r * lda + c * 8);
            cp_async16(dB + sw, Bg + (size_t)r * ldb + c * 8);
        }
    };

    // ---- warp/lane fragment geometry
    const int wm0 = (wid & 3) * 32;   // warp rows within tile
    const int wn0 = (wid >> 2) * 64;  // warp cols within tile
    const int grp = lane >> 3, rowin = lane & 7;
    // A x4 groups: (m0..7,k0) (m8..15,k0) (m0..7,k+16B) (m8..15,k+16B)
    const int a_mloc = rowin + ((grp & 1) << 3);
    const int a_koff = (grp >> 1) << 4;
    // B x4 groups: (n0..7,k0) (n0..7,k+16B) (n8..15,k0) (n8..15,k+16B)
    const int b_nloc = rowin + ((grp >> 1) << 3);
    const int b_koff = (grp & 1) << 4;

    float acc[2][8][4];
    #pragma unroll
    for (int mt = 0; mt < 2; mt++)
        #pragma unroll
        for (int nt = 0; nt < 8; nt++)
            #pragma unroll
            for (int q = 0; q < 4; q++) acc[mt][nt][q] = 0.f;

    load_stage(0, 0);
    cp_commit();
    if (nStages > 1) { load_stage(1, 1); cp_commit(); }

    for (int s = 0; s < nStages; s++) {
        if (s + 1 < nStages) cp_waitg<1>(); else cp_waitg<0>();
        __syncthreads();

        const uint32_t uA = smBase + (s & 1) * 16384;
        const uint32_t uB = smBase + 32768 + (s & 1) * 16384;
        // precomputed per-lane address pieces
        const uint32_t aRow[2] = {
            uA + (uint32_t)((wm0 + a_mloc) * 128),
            uA + (uint32_t)((wm0 + 16 + a_mloc) * 128) };
        const uint32_t aXor = (uint32_t)(((wm0 + a_mloc) & 7) << 4);   // same low3 for both m-tiles
        const uint32_t bXor = (uint32_t)(((wn0 + b_nloc) & 7) << 4);

        #pragma unroll
        for (int kk = 0; kk < 4; kk++) {
            uint32_t afr[2][4];
            #pragma unroll
            for (int mt = 0; mt < 2; mt++)
                ldsm_x4(afr[mt], aRow[mt] + (((uint32_t)(kk * 32 + a_koff)) ^ aXor));

            uint32_t bfr[8][2];
            #pragma unroll
            for (int p = 0; p < 4; p++) {
                uint32_t r4[4];
                const uint32_t bRow = uB + (uint32_t)((wn0 + p * 16 + b_nloc) * 128);
                ldsm_x4(r4, bRow + (((uint32_t)(kk * 32 + b_koff)) ^ bXor));
                bfr[2 * p][0] = r4[0]; bfr[2 * p][1] = r4[1];
                bfr[2 * p + 1][0] = r4[2]; bfr[2 * p + 1][1] = r4[3];
            }

            #pragma unroll
            for (int mt = 0; mt < 2; mt++)
                #pragma unroll
                for (int nt = 0; nt < 8; nt++)
                    mma16816(acc[mt][nt], afr[mt], bfr[nt]);
        }

        __syncthreads();
        if (s + 2 < nStages) { load_stage(s & 1, s + 2); cp_commit(); }
    }

    // ---- epilogue
    #pragma unroll
    for (int mt = 0; mt < 2; mt++) {
        const int rA = m0 + wm0 + mt * 16 + (lane >> 2);
        #pragma unroll
        for (int half = 0; half < 2; half++) {       // d0,d1 then d2,d3 (row+8)
            const int r = rA + half * 8;
            if (EPI == 1) {
                const size_t rowbase = (size_t)r * K2P;
                #pragma unroll
                for (int nt = 0; nt < 8; nt++) {
                    const int f = n0 + wn0 + nt * 8 + (lane & 3) * 2;
                    float v0 = gelu_exact(acc[mt][nt][2 * half]     + __ldg(&bias[f]));
                    float v1 = gelu_exact(acc[mt][nt][2 * half + 1] + __ldg(&bias[f + 1]));
                    __nv_bfloat16 h0 = __float2bfloat16(v0);
                    __nv_bfloat16 h1 = __float2bfloat16(v1);
                    __nv_bfloat16 l0 = __float2bfloat16(v0 - __bfloat162float(h0));
                    __nv_bfloat16 l1 = __float2bfloat16(v1 - __bfloat162float(h1));
                    __nv_bfloat162 hh; hh.x = h0; hh.y = h1;
                    __nv_bfloat162 ll; ll.x = l0; ll.y = l1;
                    *(__nv_bfloat162*)(&OutB[rowbase + f])          = hh;  // hi
                    *(__nv_bfloat162*)(&OutB[rowbase + F1 + f])     = ll;  // lo
                    *(__nv_bfloat162*)(&OutB[rowbase + 2 * F1 + f]) = hh;  // hi
                }
            } else {
                float* Cp = Cout + (size_t)z * MROWS * F2 + (size_t)r * F2;
                #pragma unroll
                for (int nt = 0; nt < 8; nt++) {
                    const int f = n0 + wn0 + nt * 8 + (lane & 3) * 2;
                    float2 v; v.x = acc[mt][nt][2 * half]; v.y = acc[mt][nt][2 * half + 1];
                    *(float2*)(Cp + f) = v;
                }
            }
        }
    }
}

// ---------------- 5) split-K reduce + bias + GELU --------------------------
__global__ void reduce_gelu_kernel(const float* __restrict__ b2) {
    const int idx = blockIdx.x * blockDim.x + threadIdx.x;
    float s = 0.f;
    #pragma unroll
    for (int i = 0; i < NSPLIT; i++) s += g_x2p[(size_t)i * MROWS * F2 + idx];
    g_x2[idx] = gelu_exact(s + b2[idx & (F2 - 1)]);
}

// ---------------- 6) head GEMM: [512,256]@[256,2] + b3 ---------------------
__global__ void head_kernel(const float* __restrict__ W3,
                            const float* __restrict__ b3,
                            float* __restrict__ out) {
    const int row = blockIdx.x;
    const int tid = threadIdx.x;
    const float x = g_x2[(size_t)row * F2 + tid];
    __shared__ float sh0[256];
    __shared__ float sh1[256];
    sh0[tid] = x * W3[tid * 2 + 0];
    sh1[tid] = x * W3[tid * 2 + 1];
    __syncthreads();
    for (int o = 128; o > 0; o >>= 1) {
        if (tid < o) { sh0[tid] += sh0[tid + o]; sh1[tid] += sh1[tid + o]; }
        __syncthreads();
    }
    if (tid == 0) {
        out[row * 2 + 0] = sh0[0] + b3[0];
        out[row * 2 + 1] = sh1[0] + b3[1];
    }
}

// ---------------- launch ----------------------------------------------------
extern "C" void kernel_launch(void* const* d_in, const int* in_sizes, int n_in,
                              void* d_out, int out_size) {
    const float* hidden = (const float*)d_in[0];
    const int*   ids32  = (const int*)  d_in[1];
    const float* W1 = (const float*)d_in[2];
    const float* b1 = (const float*)d_in[3];
    const float* W2 = (const float*)d_in[4];
    const float* b2 = (const float*)d_in[5];
    const float* W3 = (const float*)d_in[6];
    const float* b3 = (const float*)d_in[7];
    float* out = (float*)d_out;

    void *p_sentb, *p_w1b, *p_x1b, *p_w2b, *p_x2p;
    cudaGetSymbolAddress(&p_sentb, g_sentb);
    cudaGetSymbolAddress(&p_w1b,   g_w1b);
    cudaGetSymbolAddress(&p_x1b,   g_x1b);
    cudaGetSymbolAddress(&p_w2b,   g_w2b);
    cudaGetSymbolAddress(&p_x2p,   g_x2p);

    const int SMEM_DYN = 66560;   // 64KB tiles + 1KB align slack
    cudaFuncSetAttribute(mma_gemm<1>, cudaFuncAttributeMaxDynamicSharedMemorySize, SMEM_DYN);
    cudaFuncSetAttribute(mma_gemm<0>, cudaFuncAttributeMaxDynamicSharedMemorySize, SMEM_DYN);

    sep_scan_kernel<<<BB, 256>>>(ids32);
    pool_kernel<<<dim3(MS, BB), 256>>>(hidden);

    conv_w_kernel<<<dim3(F1 / 32, HH / 32), dim3(32, 8)>>>(W1, (__nv_bfloat16*)p_w1b, HH, F1);
    conv_w_kernel<<<dim3(F2 / 32, F1 / 32), dim3(32, 8)>>>(W2, (__nv_bfloat16*)p_w2b, F1, F2);

    // GEMM1: [512, 2304'] x [4096, 2304'] -> gelu -> bf16 hi/lo x1
    mma_gemm<1><<<dim3(F1 / 128, MROWS / 128, 1), 256, SMEM_DYN>>>(
        (const __nv_bfloat16*)p_sentb, K1P, (const __nv_bfloat16*)p_w1b, K1P,
        K1P / 64, b1, nullptr, (__nv_bfloat16*)p_x1b);

    // GEMM2: [512, 12288'] x [256, 12288'], split-K=16 -> fp32 partials
    mma_gemm<0><<<dim3(F2 / 128, MROWS / 128, NSPLIT), 256, SMEM_DYN>>>(
        (const __nv_bfloat16*)p_x1b, K2P, (const __nv_bfloat16*)p_w2b, K2P,
        K2P / (64 * NSPLIT), nullptr, (float*)p_x2p, nullptr);

    reduce_gelu_kernel<<<(MROWS * F2) / 256, 256>>>(b2);
    head_kernel<<<MROWS, 256>>>(W3, b3, out);
}

// round 6
// speedup vs baseline: 3.4193x; 1.1339x over previous
#include <cuda_runtime.h>
#include <cuda_bf16.h>
#include <math.h>
#include <stdint.h>

#define BB 8
#define SS 4096
#define HH 768
#define MS 64
#define F1 4096
#define F2 256
#define SEPTOK 2
#define MROWS 512          // BB*MS
#define K1P (3*HH)         // 2304 : [hi | lo | hi] along K for GEMM1
#define K2P (3*F1)         // 12288: [hi | lo | hi] along K for GEMM2
#define NSPLIT 16

// ---------------- scratch (device globals; no allocation allowed) ----------
// 1024B alignment is load-bearing: cp.async.cg 16B requires 16B-aligned
// global addresses; vector epilogue stores require 4/8/16B.
__device__ __align__(1024) __nv_bfloat16 g_sentb[MROWS * K1P];   // A' GEMM1 (hi|lo|hi)
__device__ __align__(1024) __nv_bfloat16 g_w1b[F1 * K1P];        // B' GEMM1 (W1^T: hi|hi|lo)
__device__ __align__(1024) __nv_bfloat16 g_x1b[MROWS * K2P];     // A' GEMM2 (hi|lo|hi)
__device__ __align__(1024) __nv_bfloat16 g_w2b[F2 * K2P];        // B' GEMM2 (W2^T: hi|hi|lo)
__device__ __align__(1024) float g_x2p[NSPLIT * MROWS * F2];     // split-K partials
__device__ int   g_sep_pos[BB][SS];
__device__ int   g_nsep[BB];

__device__ __forceinline__ float gelu_exact(float x) {
    return 0.5f * x * (1.0f + erff(x * 0.70710678118654752f));
}

__device__ __forceinline__ uint32_t smem_u32(const void* p) {
    uint32_t a;
    asm("{ .reg .u64 t; cvta.to.shared.u64 t, %1; cvt.u32.u64 %0, t; }" : "=r"(a) : "l"(p));
    return a;
}
__device__ __forceinline__ uint32_t sw128(uint32_t off) {
    return off ^ ((off >> 3) & 0x70);
}
__device__ __forceinline__ void cp_async16(uint32_t dst, const void* src) {
    asm volatile("cp.async.cg.shared.global [%0], [%1], 16;" :: "r"(dst), "l"(src) : "memory");
}
__device__ __forceinline__ void cp_commit() {
    asm volatile("cp.async.commit_group;" ::: "memory");
}
template<int N>
__device__ __forceinline__ void cp_waitg() {
    asm volatile("cp.async.wait_group %0;" :: "n"(N) : "memory");
}
__device__ __forceinline__ void ldsm_x4(uint32_t* r, uint32_t addr) {
    asm volatile("ldmatrix.sync.aligned.m8n8.x4.shared.b16 {%0,%1,%2,%3}, [%4];"
                 : "=r"(r[0]), "=r"(r[1]), "=r"(r[2]), "=r"(r[3]) : "r"(addr));
}
__device__ __forceinline__ void mma16816(float* d, const uint32_t* a, const uint32_t* b) {
    asm volatile(
        "mma.sync.aligned.m16n8k16.row.col.f32.bf16.bf16.f32 "
        "{%0,%1,%2,%3}, {%4,%5,%6,%7}, {%8,%9}, {%0,%1,%2,%3};"
        : "+f"(d[0]), "+f"(d[1]), "+f"(d[2]), "+f"(d[3])
        : "r"(a[0]), "r"(a[1]), "r"(a[2]), "r"(a[3]), "r"(b[0]), "r"(b[1]));
}

// ---------------- 1) sep scan (shuffle block scan) --------------------------
__global__ void sep_scan_kernel(const int* __restrict__ ids32) {
    const int b = blockIdx.x;
    const int tid = threadIdx.x;                  // 256
    const int stride = (ids32[1] == 0) ? 2 : 1;   // int64 vs int32 auto-detect
    const int* row = ids32 + (size_t)b * SS * stride;

    const int base = tid * 16;
    int c = 0;
    #pragma unroll
    for (int i = 0; i < 16; i++)
        if (row[(base + i) * stride] == SEPTOK) c++;

    const int lane = tid & 31, w = tid >> 5;
    int incl = c;
    #pragma unroll
    for (int o = 1; o < 32; o <<= 1) {
        int t = __shfl_up_sync(0xffffffffu, incl, o);
        if (lane >= o) incl += t;
    }
    __shared__ int wsum[8], woff[8];
    if (lane == 31) wsum[w] = incl;
    __syncthreads();
    if (tid == 0) {
        int a = 0;
        #pragma unroll
        for (int i = 0; i < 8; i++) { woff[i] = a; a += wsum[i]; }
        g_nsep[b] = a;
    }
    __syncthreads();

    int off = woff[w] + incl - c;
    for (int i = 0; i < 16; i++)
        if (row[(base + i) * stride] == SEPTOK)
            g_sep_pos[b][off++] = base + i;
}

// ---------------- 2) pooling (float4); emits bf16 hi/lo A' ------------------
__global__ void pool_kernel(const float* __restrict__ hidden) {
    const int s   = blockIdx.x;   // 0..63
    const int b   = blockIdx.y;   // 0..7
    const int tid = threadIdx.x;  // 192 (= HH/4)
    const int n   = g_nsep[b];

    int t0 = 0, t1 = 0;
    if (n == 0) {
        if (s == 0) { t0 = 0; t1 = SS; }
    } else if (s < n) {
        if (s == 0) { t0 = 0; t1 = g_sep_pos[b][0] + 1; }
        else        { t0 = g_sep_pos[b][s - 1] + 1; t1 = g_sep_pos[b][s]; }
    } else if (s == n) {
        t0 = g_sep_pos[b][n - 1] + 1; t1 = SS - 1;
    }

    const float4* hb = (const float4*)(hidden + (size_t)b * SS * HH);
    float4 s0 = make_float4(0.f, 0.f, 0.f, 0.f);
    float4 s1 = make_float4(0.f, 0.f, 0.f, 0.f);
    int t = t0;
    #pragma unroll 2
    for (; t + 1 < t1; t += 2) {
        float4 v0 = hb[(size_t)t * 192 + tid];
        float4 v1 = hb[(size_t)(t + 1) * 192 + tid];
        s0.x += v0.x; s0.y += v0.y; s0.z += v0.z; s0.w += v0.w;
        s1.x += v1.x; s1.y += v1.y; s1.z += v1.z; s1.w += v1.w;
    }
    if (t < t1) {
        float4 v0 = hb[(size_t)t * 192 + tid];
        s0.x += v0.x; s0.y += v0.y; s0.z += v0.z; s0.w += v0.w;
    }
    const int cnt = t1 - t0;
    const float inv = (cnt > 0) ? (1.0f / (float)cnt) : 0.0f;
    float v[4] = { (s0.x + s1.x) * inv, (s0.y + s1.y) * inv,
                   (s0.z + s1.z) * inv, (s0.w + s1.w) * inv };

    __nv_bfloat162 hh[2], ll[2];
    #pragma unroll
    for (int q = 0; q < 2; q++) {
        __nv_bfloat16 h0 = __float2bfloat16(v[2 * q]);
        __nv_bfloat16 h1 = __float2bfloat16(v[2 * q + 1]);
        hh[q].x = h0; hh[q].y = h1;
        ll[q].x = __float2bfloat16(v[2 * q]     - __bfloat162float(h0));
        ll[q].y = __float2bfloat16(v[2 * q + 1] - __bfloat162float(h1));
    }
    const size_t rb = (size_t)(b * MS + s) * K1P + tid * 4;
    #pragma unroll
    for (int q = 0; q < 2; q++) {
        *(__nv_bfloat162*)(&g_sentb[rb + 2 * q])            = hh[q];  // chunk 0: hi
        *(__nv_bfloat162*)(&g_sentb[rb + HH + 2 * q])       = ll[q];  // chunk 1: lo
        *(__nv_bfloat162*)(&g_sentb[rb + 2 * HH + 2 * q])   = hh[q];  // chunk 2: hi
    }
}

// ---------------- 3) weight transpose + hi/lo split -------------------------
// W: [K, N] row-major  ->  out: [N, 3K] bf16 with [hi | hi | lo]
__global__ void conv_w_kernel(const float* __restrict__ W, __nv_bfloat16* __restrict__ out,
                              int K, int N) {
    __shared__ float t[32][33];
    const int n0 = blockIdx.x * 32, k0 = blockIdx.y * 32;
    const int tx = threadIdx.x, ty = threadIdx.y;   // 32 x 8
    #pragma unroll
    for (int i = 0; i < 4; i++)
        t[ty + i * 8][tx] = W[(size_t)(k0 + ty + i * 8) * N + n0 + tx];
    __syncthreads();
    #pragma unroll
    for (int i = 0; i < 4; i++) {
        const int nn = n0 + ty + i * 8;
        const float v = t[tx][ty + i * 8];            // = W[k0+tx][nn]
        __nv_bfloat16 h = __float2bfloat16(v);
        __nv_bfloat16 l = __float2bfloat16(v - __bfloat162float(h));
        const size_t base = (size_t)nn * (3 * (size_t)K) + k0 + tx;
        out[base]         = h;   // chunk 0: hi
        out[base + K]     = h;   // chunk 1: hi (pairs with A-lo)
        out[base + 2 * K] = l;   // chunk 2: lo (pairs with A-hi)
    }
}

// ---------------- 4) mma.sync bf16 GEMM, 128x128 tile, K staged 128 ---------
// 3-deep cp.async ring (no trailing barrier). A: [M,lda] K-major bf16,
// B: [N,ldb] K-major bf16 (B^T). 8 warps, 4(m)x2(n), warp tile 32x64.
// EPI==1: D + bias -> GELU -> bf16 hi/lo A' for GEMM2.  EPI==0: fp32 partials.
template<int EPI>
__global__ __launch_bounds__(256)
void mma_gemm(const __nv_bfloat16* __restrict__ A, int lda,
              const __nv_bfloat16* __restrict__ Bm, int ldb,
              int nStages,            // number of 128-wide K stages
              const float* __restrict__ bias,
              float* __restrict__ Cout,
              __nv_bfloat16* __restrict__ OutB)
{
    extern __shared__ char dsm_raw[];
    char* dsm = (char*)(((uintptr_t)dsm_raw + 1023) & ~(uintptr_t)1023);

    const int tid  = threadIdx.x;
    const int wid  = tid >> 5, lane = tid & 31;
    const int m0   = blockIdx.y * 128;
    const int n0   = blockIdx.x * 128;
    const int z    = blockIdx.z;
    const int ks0  = z * nStages * 128;

    const uint32_t smBase = smem_u32(dsm);
    // buffers: A at buf*32768 (+sub*16384), B at 98304 + buf*32768 (+sub*16384)

    auto load_stage = [&](int buf, int s) {
        const int ko = ks0 + s * 128;
        const uint32_t dA = smBase + buf * 32768;
        const uint32_t dB = smBase + 98304 + buf * 32768;
        #pragma unroll
        for (int sub = 0; sub < 2; sub++) {
            const __nv_bfloat16* Ag = A  + (size_t)m0 * lda + ko + sub * 64;
            const __nv_bfloat16* Bg = Bm + (size_t)n0 * ldb + ko + sub * 64;
            #pragma unroll
            for (int i = 0; i < 4; i++) {
                const int ch = tid + i * 256;           // 1024 16B chunks / sub-tile
                const int r = ch >> 3, c = ch & 7;
                const uint32_t sw = sw128((uint32_t)(r * 128 + c * 16)) + sub * 16384;
                cp_async16(dA + sw, Ag + (size_t)r * lda + c * 8);
                cp_async16(dB + sw, Bg + (size_t)r * ldb + c * 8);
            }
        }
    };

    // ---- warp/lane fragment geometry
    const int wm0 = (wid & 3) * 32;
    const int wn0 = (wid >> 2) * 64;
    const int grp = lane >> 3, rowin = lane & 7;
    const int a_mloc = rowin + ((grp & 1) << 3);
    const int a_koff = (grp >> 1) << 4;
    const int b_nloc = rowin + ((grp >> 1) << 3);
    const int b_koff = (grp & 1) << 4;

    float acc[2][8][4];
    #pragma unroll
    for (int mt = 0; mt < 2; mt++)
        #pragma unroll
        for (int nt = 0; nt < 8; nt++)
            #pragma unroll
            for (int q = 0; q < 4; q++) acc[mt][nt][q] = 0.f;

    load_stage(0, 0);
    cp_commit();
    if (nStages > 1) { load_stage(1, 1); cp_commit(); }

    int buf = 0;
    for (int s = 0; s < nStages; s++) {
        if (s + 1 < nStages) cp_waitg<1>(); else cp_waitg<0>();
        __syncthreads();

        #pragma unroll
        for (int sub = 0; sub < 2; sub++) {
            const uint32_t uA = smBase + buf * 32768 + sub * 16384;
            const uint32_t uB = smBase + 98304 + buf * 32768 + sub * 16384;
            const uint32_t aRow[2] = {
                uA + (uint32_t)((wm0 + a_mloc) * 128),
                uA + (uint32_t)((wm0 + 16 + a_mloc) * 128) };
            const uint32_t aXor = (uint32_t)(((wm0 + a_mloc) & 7) << 4);
            const uint32_t bXor = (uint32_t)(((wn0 + b_nloc) & 7) << 4);

            #pragma unroll
            for (int kk = 0; kk < 4; kk++) {
                uint32_t afr[2][4];
                #pragma unroll
                for (int mt = 0; mt < 2; mt++)
                    ldsm_x4(afr[mt], aRow[mt] + (((uint32_t)(kk * 32 + a_koff)) ^ aXor));

                uint32_t bfr[8][2];
                #pragma unroll
                for (int p = 0; p < 4; p++) {
                    uint32_t r4[4];
                    const uint32_t bRow = uB + (uint32_t)((wn0 + p * 16 + b_nloc) * 128);
                    ldsm_x4(r4, bRow + (((uint32_t)(kk * 32 + b_koff)) ^ bXor));
                    bfr[2 * p][0] = r4[0]; bfr[2 * p][1] = r4[1];
                    bfr[2 * p + 1][0] = r4[2]; bfr[2 * p + 1][1] = r4[3];
                }

                #pragma unroll
                for (int mt = 0; mt < 2; mt++)
                    #pragma unroll
                    for (int nt = 0; nt < 8; nt++)
                        mma16816(acc[mt][nt], afr[mt], bfr[nt]);
            }
        }

        // 3-buffer ring: overwrite target was consumed at stage s-1; the
        // top-of-loop barrier for stage s already fenced all its readers.
        if (s + 2 < nStages) { load_stage((s + 2) % 3, s + 2); cp_commit(); }
        buf = (buf + 1) % 3;
    }

    // ---- epilogue
    #pragma unroll
    for (int mt = 0; mt < 2; mt++) {
        const int rA = m0 + wm0 + mt * 16 + (lane >> 2);
        #pragma unroll
        for (int half = 0; half < 2; half++) {
            const int r = rA + half * 8;
            if (EPI == 1) {
                const size_t rowbase = (size_t)r * K2P;
                #pragma unroll
                for (int nt = 0; nt < 8; nt++) {
                    const int f = n0 + wn0 + nt * 8 + (lane & 3) * 2;
                    float v0 = gelu_exact(acc[mt][nt][2 * half]     + __ldg(&bias[f]));
                    float v1 = gelu_exact(acc[mt][nt][2 * half + 1] + __ldg(&bias[f + 1]));
                    __nv_bfloat16 h0 = __float2bfloat16(v0);
                    __nv_bfloat16 h1 = __float2bfloat16(v1);
                    __nv_bfloat16 l0 = __float2bfloat16(v0 - __bfloat162float(h0));
                    __nv_bfloat16 l1 = __float2bfloat16(v1 - __bfloat162float(h1));
                    __nv_bfloat162 hh; hh.x = h0; hh.y = h1;
                    __nv_bfloat162 ll; ll.x = l0; ll.y = l1;
                    *(__nv_bfloat162*)(&OutB[rowbase + f])          = hh;  // hi
                    *(__nv_bfloat162*)(&OutB[rowbase + F1 + f])     = ll;  // lo
                    *(__nv_bfloat162*)(&OutB[rowbase + 2 * F1 + f]) = hh;  // hi
                }
            } else {
                float* Cp = Cout + (size_t)z * MROWS * F2 + (size_t)r * F2;
                #pragma unroll
                for (int nt = 0; nt < 8; nt++) {
                    const int f = n0 + wn0 + nt * 8 + (lane & 3) * 2;
                    float2 v; v.x = acc[mt][nt][2 * half]; v.y = acc[mt][nt][2 * half + 1];
                    *(float2*)(Cp + f) = v;
                }
            }
        }
    }
}

// ---------------- 5) fused split-K reduce + bias + GELU + head --------------
// one block per row: x2 = gelu(sum_z partials + b2); out = x2 @ W3 + b3
__global__ void reduce_head_kernel(const float* __restrict__ b2,
                                   const float* __restrict__ W3,
                                   const float* __restrict__ b3,
                                   float* __restrict__ out) {
    const int row = blockIdx.x;   // 512
    const int tid = threadIdx.x;  // 256
    const int idx = row * F2 + tid;
    float s = 0.f;
    #pragma unroll
    for (int i = 0; i < NSPLIT; i++) s += g_x2p[(size_t)i * MROWS * F2 + idx];
    const float x = gelu_exact(s + b2[tid]);

    __shared__ float sh0[256];
    __shared__ float sh1[256];
    sh0[tid] = x * W3[tid * 2 + 0];
    sh1[tid] = x * W3[tid * 2 + 1];
    __syncthreads();
    for (int o = 128; o > 0; o >>= 1) {
        if (tid < o) { sh0[tid] += sh0[tid + o]; sh1[tid] += sh1[tid + o]; }
        __syncthreads();
    }
    if (tid == 0) {
        out[row * 2 + 0] = sh0[0] + b3[0];
        out[row * 2 + 1] = sh1[0] + b3[1];
    }
}

// ---------------- launch ----------------------------------------------------
extern "C" void kernel_launch(void* const* d_in, const int* in_sizes, int n_in,
                              void* d_out, int out_size) {
    const float* hidden = (const float*)d_in[0];
    const int*   ids32  = (const int*)  d_in[1];
    const float* W1 = (const float*)d_in[2];
    const float* b1 = (const float*)d_in[3];
    const float* W2 = (const float*)d_in[4];
    const float* b2 = (const float*)d_in[5];
    const float* W3 = (const float*)d_in[6];
    const float* b3 = (const float*)d_in[7];
    float* out = (float*)d_out;

    void *p_sentb, *p_w1b, *p_x1b, *p_w2b, *p_x2p;
    cudaGetSymbolAddress(&p_sentb, g_sentb);
    cudaGetSymbolAddress(&p_w1b,   g_w1b);
    cudaGetSymbolAddress(&p_x1b,   g_x1b);
    cudaGetSymbolAddress(&p_w2b,   g_w2b);
    cudaGetSymbolAddress(&p_x2p,   g_x2p);

    const int SMEM_DYN = 197632;   // 3 x (32KB A + 32KB B) + 1KB align slack
    cudaFuncSetAttribute(mma_gemm<1>, cudaFuncAttributeMaxDynamicSharedMemorySize, SMEM_DYN);
    cudaFuncSetAttribute(mma_gemm<0>, cudaFuncAttributeMaxDynamicSharedMemorySize, SMEM_DYN);

    sep_scan_kernel<<<BB, 256>>>(ids32);
    pool_kernel<<<dim3(MS, BB), 192>>>(hidden);

    conv_w_kernel<<<dim3(F1 / 32, HH / 32), dim3(32, 8)>>>(W1, (__nv_bfloat16*)p_w1b, HH, F1);
    conv_w_kernel<<<dim3(F2 / 32, F1 / 32), dim3(32, 8)>>>(W2, (__nv_bfloat16*)p_w2b, F1, F2);

    // GEMM1: [512, 2304'] x [4096, 2304'] -> gelu -> bf16 hi/lo x1  (18 stages)
    mma_gemm<1><<<dim3(F1 / 128, MROWS / 128, 1), 256, SMEM_DYN>>>(
        (const __nv_bfloat16*)p_sentb, K1P, (const __nv_bfloat16*)p_w1b, K1P,
        K1P / 128, b1, nullptr, (__nv_bfloat16*)p_x1b);

    // GEMM2: [512, 12288'] x [256, 12288'], split-K=16 -> fp32 partials (6 stages)
    mma_gemm<0><<<dim3(F2 / 128, MROWS / 128, NSPLIT), 256, SMEM_DYN>>>(
        (const __nv_bfloat16*)p_x1b, K2P, (const __nv_bfloat16*)p_w2b, K2P,
        K2P / (128 * NSPLIT), nullptr, (float*)p_x2p, nullptr);

    reduce_head_kernel<<<MROWS, 256>>>(b2, W3, b3, out);
}

// round 7
// speedup vs baseline: 4.0621x; 1.1880x over previous
#include <cuda_runtime.h>
#include <cuda_fp16.h>
#include <math.h>
#include <stdint.h>

#define BB 8
#define SS 4096
#define HH 768
#define MS 64
#define F1 4096
#define F2 256
#define SEPTOK 2
#define MROWS 512          // BB*MS
#define K1P (2*HH)         // 1536 : A'=[hi|lo] fp16 along K for GEMM1
#define K2P (2*F1)         // 8192 : A'=[hi|lo] fp16 along K for GEMM2
#define NSPLIT 16

// ---------------- scratch (device globals; no allocation allowed) ----------
// 1024B alignment is load-bearing: cp.async.cg 16B requires 16B-aligned
// global addresses; vector epilogue stores require 4/8/16B.
__device__ __align__(1024) __half g_sentb[MROWS * K1P];   // A' GEMM1 [Ah|Al]
__device__ __align__(1024) __half g_w1b[F1 * HH];         // B GEMM1: W1^T hi only
__device__ __align__(1024) __half g_x1b[MROWS * K2P];     // A' GEMM2 [hi|lo]
__device__ __align__(1024) __half g_w2b[F2 * F1];         // B GEMM2: W2^T hi only
__device__ __align__(1024) float g_x2p[NSPLIT * MROWS * F2];   // split-K partials
__device__ int   g_sep_pos[BB][SS];
__device__ int   g_nsep[BB];

__device__ __forceinline__ float gelu_exact(float x) {
    return 0.5f * x * (1.0f + erff(x * 0.70710678118654752f));
}

__device__ __forceinline__ uint32_t smem_u32(const void* p) {
    uint32_t a;
    asm("{ .reg .u64 t; cvta.to.shared.u64 t, %1; cvt.u32.u64 %0, t; }" : "=r"(a) : "l"(p));
    return a;
}
__device__ __forceinline__ uint32_t sw128(uint32_t off) {
    return off ^ ((off >> 3) & 0x70);
}
__device__ __forceinline__ void cp_async16(uint32_t dst, const void* src) {
    asm volatile("cp.async.cg.shared.global [%0], [%1], 16;" :: "r"(dst), "l"(src) : "memory");
}
__device__ __forceinline__ void cp_commit() {
    asm volatile("cp.async.commit_group;" ::: "memory");
}
template<int N>
__device__ __forceinline__ void cp_waitg() {
    asm volatile("cp.async.wait_group %0;" :: "n"(N) : "memory");
}
__device__ __forceinline__ void ldsm_x4(uint32_t* r, uint32_t addr) {
    asm volatile("ldmatrix.sync.aligned.m8n8.x4.shared.b16 {%0,%1,%2,%3}, [%4];"
                 : "=r"(r[0]), "=r"(r[1]), "=r"(r[2]), "=r"(r[3]) : "r"(addr));
}
__device__ __forceinline__ void mma16816(float* d, const uint32_t* a, const uint32_t* b) {
    asm volatile(
        "mma.sync.aligned.m16n8k16.row.col.f32.f16.f16.f32 "
        "{%0,%1,%2,%3}, {%4,%5,%6,%7}, {%8,%9}, {%0,%1,%2,%3};"
        : "+f"(d[0]), "+f"(d[1]), "+f"(d[2]), "+f"(d[3])
        : "r"(a[0]), "r"(a[1]), "r"(a[2]), "r"(a[3]), "r"(b[0]), "r"(b[1]));
}

// ---------------- 1) sep scan (shuffle block scan) --------------------------
__global__ void sep_scan_kernel(const int* __restrict__ ids32) {
    const int b = blockIdx.x;
    const int tid = threadIdx.x;                  // 256
    const int stride = (ids32[1] == 0) ? 2 : 1;   // int64 vs int32 auto-detect
    const int* row = ids32 + (size_t)b * SS * stride;

    const int base = tid * 16;
    int c = 0;
    #pragma unroll
    for (int i = 0; i < 16; i++)
        if (row[(base + i) * stride] == SEPTOK) c++;

    const int lane = tid & 31, w = tid >> 5;
    int incl = c;
    #pragma unroll
    for (int o = 1; o < 32; o <<= 1) {
        int t = __shfl_up_sync(0xffffffffu, incl, o);
        if (lane >= o) incl += t;
    }
    __shared__ int wsum[8], woff[8];
    if (lane == 31) wsum[w] = incl;
    __syncthreads();
    if (tid == 0) {
        int a = 0;
        #pragma unroll
        for (int i = 0; i < 8; i++) { woff[i] = a; a += wsum[i]; }
        g_nsep[b] = a;
    }
    __syncthreads();

    int off = woff[w] + incl - c;
    for (int i = 0; i < 16; i++)
        if (row[(base + i) * stride] == SEPTOK)
            g_sep_pos[b][off++] = base + i;
}

// ---------------- 2) pooling (float4, x4 unroll); emits fp16 hi/lo A' -------
__global__ void pool_kernel(const float* __restrict__ hidden) {
    const int s   = blockIdx.x;   // 0..63
    const int b   = blockIdx.y;   // 0..7
    const int tid = threadIdx.x;  // 192 (= HH/4)
    const int n   = g_nsep[b];

    int t0 = 0, t1 = 0;
    if (n == 0) {
        if (s == 0) { t0 = 0; t1 = SS; }
    } else if (s < n) {
        if (s == 0) { t0 = 0; t1 = g_sep_pos[b][0] + 1; }
        else        { t0 = g_sep_pos[b][s - 1] + 1; t1 = g_sep_pos[b][s]; }
    } else if (s == n) {
        t0 = g_sep_pos[b][n - 1] + 1; t1 = SS - 1;
    }

    const float4* hb = (const float4*)(hidden + (size_t)b * SS * HH);
    float4 s0 = make_float4(0.f,0.f,0.f,0.f), s1 = s0, s2 = s0, s3 = s0;
    int t = t0;
    for (; t + 3 < t1; t += 4) {
        float4 v0 = hb[(size_t)t * 192 + tid];
        float4 v1 = hb[(size_t)(t + 1) * 192 + tid];
        float4 v2 = hb[(size_t)(t + 2) * 192 + tid];
        float4 v3 = hb[(size_t)(t + 3) * 192 + tid];
        s0.x += v0.x; s0.y += v0.y; s0.z += v0.z; s0.w += v0.w;
        s1.x += v1.x; s1.y += v1.y; s1.z += v1.z; s1.w += v1.w;
        s2.x += v2.x; s2.y += v2.y; s2.z += v2.z; s2.w += v2.w;
        s3.x += v3.x; s3.y += v3.y; s3.z += v3.z; s3.w += v3.w;
    }
    for (; t < t1; t++) {
        float4 v0 = hb[(size_t)t * 192 + tid];
        s0.x += v0.x; s0.y += v0.y; s0.z += v0.z; s0.w += v0.w;
    }
    const int cnt = t1 - t0;
    const float inv = (cnt > 0) ? (1.0f / (float)cnt) : 0.0f;
    float v[4] = { (s0.x + s1.x + s2.x + s3.x) * inv,
                   (s0.y + s1.y + s2.y + s3.y) * inv,
                   (s0.z + s1.z + s2.z + s3.z) * inv,
                   (s0.w + s1.w + s2.w + s3.w) * inv };

    __half2 hh[2], ll[2];
    #pragma unroll
    for (int q = 0; q < 2; q++) {
        __half h0 = __float2half(v[2 * q]);
        __half h1 = __float2half(v[2 * q + 1]);
        hh[q] = __halves2half2(h0, h1);
        ll[q] = __halves2half2(__float2half(v[2 * q]     - __half2float(h0)),
                               __float2half(v[2 * q + 1] - __half2float(h1)));
    }
    const size_t rb = (size_t)(b * MS + s) * K1P + tid * 4;
    #pragma unroll
    for (int q = 0; q < 2; q++) {
        *(__half2*)(&g_sentb[rb + 2 * q])        = hh[q];   // chunk 0: hi
        *(__half2*)(&g_sentb[rb + HH + 2 * q])   = ll[q];   // chunk 1: lo
    }
}

// ---------------- 3) weight transpose, fp16 hi only -------------------------
// W: [K, N] row-major  ->  out: [N, K] fp16
__global__ void conv_w_kernel(const float* __restrict__ W, __half* __restrict__ out,
                              int K, int N) {
    __shared__ float t[32][33];
    const int n0 = blockIdx.x * 32, k0 = blockIdx.y * 32;
    const int tx = threadIdx.x, ty = threadIdx.y;   // 32 x 8
    #pragma unroll
    for (int i = 0; i < 4; i++)
        t[ty + i * 8][tx] = W[(size_t)(k0 + ty + i * 8) * N + n0 + tx];
    __syncthreads();
    #pragma unroll
    for (int i = 0; i < 4; i++) {
        const int nn = n0 + ty + i * 8;
        out[(size_t)nn * K + k0 + tx] = __float2half(t[tx][ty + i * 8]);
    }
}

// ---------------- 4) mma.sync fp16 GEMM, 128x128 tile, K staged 128 ---------
// 2-term split: A'=[Ah|Al] (lda = 2*Kphys), B physical hi-only [N, bKphys],
// logically duplicated along K via (ko % bKphys). 3-deep cp.async ring.
// EPI==1: D + bias -> GELU -> fp16 hi/lo A' for GEMM2.  EPI==0: fp32 partials.
template<int EPI>
__global__ __launch_bounds__(256)
void mma_gemm(const __half* __restrict__ A, int lda,
              const __half* __restrict__ Bm, int bKphys,
              int nStages,            // number of 128-wide logical K stages
              const float* __restrict__ bias,
              float* __restrict__ Cout,
              __half* __restrict__ OutB)
{
    extern __shared__ char dsm_raw[];
    char* dsm = (char*)(((uintptr_t)dsm_raw + 1023) & ~(uintptr_t)1023);

    const int tid  = threadIdx.x;
    const int wid  = tid >> 5, lane = tid & 31;
    const int m0   = blockIdx.y * 128;
    const int n0   = blockIdx.x * 128;
    const int z    = blockIdx.z;
    const int ks0  = z * nStages * 128;

    const uint32_t smBase = smem_u32(dsm);

    auto load_stage = [&](int buf, int s) {
        const int ko = ks0 + s * 128;
        const int kb = ko % bKphys;               // B hi-plane duplication
        const uint32_t dA = smBase + buf * 32768;
        const uint32_t dB = smBase + 98304 + buf * 32768;
        #pragma unroll
        for (int sub = 0; sub < 2; sub++) {
            const __half* Ag = A  + (size_t)m0 * lda + ko + sub * 64;
            const __half* Bg = Bm + (size_t)n0 * bKphys + kb + sub * 64;
            #pragma unroll
            for (int i = 0; i < 4; i++) {
                const int ch = tid + i * 256;     // 1024 16B chunks / sub-tile
                const int r = ch >> 3, c = ch & 7;
                const uint32_t sw = sw128((uint32_t)(r * 128 + c * 16)) + sub * 16384;
                cp_async16(dA + sw, Ag + (size_t)r * lda + c * 8);
                cp_async16(dB + sw, Bg + (size_t)r * bKphys + c * 8);
            }
        }
    };

    // ---- warp/lane fragment geometry
    const int wm0 = (wid & 3) * 32;
    const int wn0 = (wid >> 2) * 64;
    const int grp = lane >> 3, rowin = lane & 7;
    const int a_mloc = rowin + ((grp & 1) << 3);
    const int a_koff = (grp >> 1) << 4;
    const int b_nloc = rowin + ((grp >> 1) << 3);
    const int b_koff = (grp & 1) << 4;

    float acc[2][8][4];
    #pragma unroll
    for (int mt = 0; mt < 2; mt++)
        #pragma unroll
        for (int nt = 0; nt < 8; nt++)
            #pragma unroll
            for (int q = 0; q < 4; q++) acc[mt][nt][q] = 0.f;

    load_stage(0, 0);
    cp_commit();
    if (nStages > 1) { load_stage(1, 1); cp_commit(); }

    int buf = 0;
    for (int s = 0; s < nStages; s++) {
        if (s + 1 < nStages) cp_waitg<1>(); else cp_waitg<0>();
        __syncthreads();

        #pragma unroll
        for (int sub = 0; sub < 2; sub++) {
            const uint32_t uA = smBase + buf * 32768 + sub * 16384;
            const uint32_t uB = smBase + 98304 + buf * 32768 + sub * 16384;
            const uint32_t aRow[2] = {
                uA + (uint32_t)((wm0 + a_mloc) * 128),
                uA + (uint32_t)((wm0 + 16 + a_mloc) * 128) };
            const uint32_t aXor = (uint32_t)(((wm0 + a_mloc) & 7) << 4);
            const uint32_t bXor = (uint32_t)(((wn0 + b_nloc) & 7) << 4);

            #pragma unroll
            for (int kk = 0; kk < 4; kk++) {
                uint32_t afr[2][4];
                #pragma unroll
                for (int mt = 0; mt < 2; mt++)
                    ldsm_x4(afr[mt], aRow[mt] + (((uint32_t)(kk * 32 + a_koff)) ^ aXor));

                uint32_t bfr[8][2];
                #pragma unroll
                for (int p = 0; p < 4; p++) {
                    uint32_t r4[4];
                    const uint32_t bRow = uB + (uint32_t)((wn0 + p * 16 + b_nloc) * 128);
                    ldsm_x4(r4, bRow + (((uint32_t)(kk * 32 + b_koff)) ^ bXor));
                    bfr[2 * p][0] = r4[0]; bfr[2 * p][1] = r4[1];
                    bfr[2 * p + 1][0] = r4[2]; bfr[2 * p + 1][1] = r4[3];
                }

                #pragma unroll
                for (int mt = 0; mt < 2; mt++)
                    #pragma unroll
                    for (int nt = 0; nt < 8; nt++)
                        mma16816(acc[mt][nt], afr[mt], bfr[nt]);
            }
        }

        // 3-buffer ring: overwrite target was consumed at stage s-1; the
        // top-of-loop barrier for stage s already fenced all its readers.
        if (s + 2 < nStages) { load_stage((s + 2) % 3, s + 2); cp_commit(); }
        buf = (buf + 1) % 3;
    }

    // ---- epilogue
    #pragma unroll
    for (int mt = 0; mt < 2; mt++) {
        const int rA = m0 + wm0 + mt * 16 + (lane >> 2);
        #pragma unroll
        for (int half = 0; half < 2; half++) {
            const int r = rA + half * 8;
            if (EPI == 1) {
                const size_t rowbase = (size_t)r * K2P;
                #pragma unroll
                for (int nt = 0; nt < 8; nt++) {
                    const int f = n0 + wn0 + nt * 8 + (lane & 3) * 2;
                    float v0 = gelu_exact(acc[mt][nt][2 * half]     + __ldg(&bias[f]));
                    float v1 = gelu_exact(acc[mt][nt][2 * half + 1] + __ldg(&bias[f + 1]));
                    __half h0 = __float2half(v0);
                    __half h1 = __float2half(v1);
                    __half2 hh = __halves2half2(h0, h1);
                    __half2 ll = __halves2half2(__float2half(v0 - __half2float(h0)),
                                                __float2half(v1 - __half2float(h1)));
                    *(__half2*)(&OutB[rowbase + f])      = hh;   // hi
                    *(__half2*)(&OutB[rowbase + F1 + f]) = ll;   // lo
                }
            } else {
                float* Cp = Cout + (size_t)z * MROWS * F2 + (size_t)r * F2;
                #pragma unroll
                for (int nt = 0; nt < 8; nt++) {
                    const int f = n0 + wn0 + nt * 8 + (lane & 3) * 2;
                    float2 v; v.x = acc[mt][nt][2 * half]; v.y = acc[mt][nt][2 * half + 1];
                    *(float2*)(Cp + f) = v;
                }
            }
        }
    }
}

// ---------------- 5) fused split-K reduce + bias + GELU + head --------------
__global__ void reduce_head_kernel(const float* __restrict__ b2,
                                   const float* __restrict__ W3,
                                   const float* __restrict__ b3,
                                   float* __restrict__ out) {
    const int row = blockIdx.x;   // 512
    const int tid = threadIdx.x;  // 256
    const int idx = row * F2 + tid;
    float s = 0.f;
    #pragma unroll
    for (int i = 0; i < NSPLIT; i++) s += g_x2p[(size_t)i * MROWS * F2 + idx];
    const float x = gelu_exact(s + b2[tid]);

    __shared__ float sh0[256];
    __shared__ float sh1[256];
    sh0[tid] = x * W3[tid * 2 + 0];
    sh1[tid] = x * W3[tid * 2 + 1];
    __syncthreads();
    for (int o = 128; o > 0; o >>= 1) {
        if (tid < o) { sh0[tid] += sh0[tid + o]; sh1[tid] += sh1[tid + o]; }
        __syncthreads();
    }
    if (tid == 0) {
        out[row * 2 + 0] = sh0[0] + b3[0];
        out[row * 2 + 1] = sh1[0] + b3[1];
    }
}

// ---------------- launch ----------------------------------------------------
extern "C" void kernel_launch(void* const* d_in, const int* in_sizes, int n_in,
                              void* d_out, int out_size) {
    const float* hidden = (const float*)d_in[0];
    const int*   ids32  = (const int*)  d_in[1];
    const float* W1 = (const float*)d_in[2];
    const float* b1 = (const float*)d_in[3];
    const float* W2 = (const float*)d_in[4];
    const float* b2 = (const float*)d_in[5];
    const float* W3 = (const float*)d_in[6];
    const float* b3 = (const float*)d_in[7];
    float* out = (float*)d_out;

    void *p_sentb, *p_w1b, *p_x1b, *p_w2b, *p_x2p;
    cudaGetSymbolAddress(&p_sentb, g_sentb);
    cudaGetSymbolAddress(&p_w1b,   g_w1b);
    cudaGetSymbolAddress(&p_x1b,   g_x1b);
    cudaGetSymbolAddress(&p_w2b,   g_w2b);
    cudaGetSymbolAddress(&p_x2p,   g_x2p);

    const int SMEM_DYN = 197632;   // 3 x (32KB A + 32KB B) + 1KB align slack
    cudaFuncSetAttribute(mma_gemm<1>, cudaFuncAttributeMaxDynamicSharedMemorySize, SMEM_DYN);
    cudaFuncSetAttribute(mma_gemm<0>, cudaFuncAttributeMaxDynamicSharedMemorySize, SMEM_DYN);

    sep_scan_kernel<<<BB, 256>>>(ids32);
    pool_kernel<<<dim3(MS, BB), 192>>>(hidden);

    conv_w_kernel<<<dim3(F1 / 32, HH / 32), dim3(32, 8)>>>(W1, (__half*)p_w1b, HH, F1);
    conv_w_kernel<<<dim3(F2 / 32, F1 / 32), dim3(32, 8)>>>(W2, (__half*)p_w2b, F1, F2);

    // GEMM1: [512, 1536'] x B-hi[4096, 768] -> gelu -> fp16 hi/lo x1  (12 stages)
    mma_gemm<1><<<dim3(F1 / 128, MROWS / 128, 1), 256, SMEM_DYN>>>(
        (const __half*)p_sentb, K1P, (const __half*)p_w1b, HH,
        K1P / 128, b1, nullptr, (__half*)p_x1b);

    // GEMM2: [512, 8192'] x B-hi[256, 4096], split-K=16 -> fp32 partials (4 stages)
    mma_gemm<0><<<dim3(F2 / 128, MROWS / 128, NSPLIT), 256, SMEM_DYN>>>(
        (const __half*)p_x1b, K2P, (const __half*)p_w2b, F1,
        K2P / (128 * NSPLIT), nullptr, (float*)p_x2p, nullptr);

    reduce_head_kernel<<<MROWS, 256>>>(b2, W3, b3, out);
}

// round 9
// speedup vs baseline: 5.0840x; 1.2516x over previous
#include <cuda_runtime.h>
#include <cuda_fp16.h>
#include <math.h>
#include <stdint.h>

#define BB 8
#define SS 4096
#define HH 768
#define MS 64
#define F1 4096
#define F2 256
#define SEPTOK 2
#define MROWS 512          // BB*MS
#define NSPLIT 16

// ---------------- scratch (device globals; no allocation allowed) ----------
// 1024B alignment is load-bearing: cp.async.cg 16B requires 16B-aligned
// global addresses; vector epilogue stores require 4/8/16B.
__device__ __align__(1024) __half g_sentb[MROWS * HH];    // A GEMM1, fp16
__device__ __align__(1024) __half g_w1b[F1 * HH];         // B GEMM1: W1^T fp16
__device__ __align__(1024) __half g_x1b[MROWS * F1];      // A GEMM2, fp16
__device__ __align__(1024) __half g_w2b[F2 * F1];         // B GEMM2: W2^T fp16
__device__ __align__(1024) float g_x2p[NSPLIT * MROWS * F2];   // split-K partials
__device__ int   g_sep_pos[BB][SS];
__device__ int   g_nsep[BB];

__device__ __forceinline__ float gelu_exact(float x) {
    return 0.5f * x * (1.0f + erff(x * 0.70710678118654752f));
}

__device__ __forceinline__ uint32_t smem_u32(const void* p) {
    uint32_t a;
    asm("{ .reg .u64 t; cvta.to.shared.u64 t, %1; cvt.u32.u64 %0, t; }" : "=r"(a) : "l"(p));
    return a;
}
__device__ __forceinline__ uint32_t sw128(uint32_t off) {
    return off ^ ((off >> 3) & 0x70);
}
__device__ __forceinline__ void cp_async16(uint32_t dst, const void* src) {
    asm volatile("cp.async.cg.shared.global [%0], [%1], 16;" :: "r"(dst), "l"(src) : "memory");
}
__device__ __forceinline__ void cp_commit() {
    asm volatile("cp.async.commit_group;" ::: "memory");
}
template<int N>
__device__ __forceinline__ void cp_waitg() {
    asm volatile("cp.async.wait_group %0;" :: "n"(N) : "memory");
}
__device__ __forceinline__ void ldsm_x4(uint32_t* r, uint32_t addr) {
    asm volatile("ldmatrix.sync.aligned.m8n8.x4.shared.b16 {%0,%1,%2,%3}, [%4];"
                 : "=r"(r[0]), "=r"(r[1]), "=r"(r[2]), "=r"(r[3]) : "r"(addr));
}
__device__ __forceinline__ void mma16816(float* d, const uint32_t* a, const uint32_t* b) {
    asm volatile(
        "mma.sync.aligned.m16n8k16.row.col.f32.f16.f16.f32 "
        "{%0,%1,%2,%3}, {%4,%5,%6,%7}, {%8,%9}, {%0,%1,%2,%3};"
        : "+f"(d[0]), "+f"(d[1]), "+f"(d[2]), "+f"(d[3])
        : "r"(a[0]), "r"(a[1]), "r"(a[2]), "r"(a[3]), "r"(b[0]), "r"(b[1]));
}

// ---------------- 1) sep scan (shuffle block scan) --------------------------
__global__ void sep_scan_kernel(const int* __restrict__ ids32) {
    const int b = blockIdx.x;
    const int tid = threadIdx.x;                  // 256
    const int stride = (ids32[1] == 0) ? 2 : 1;   // int64 vs int32 auto-detect
    const int* row = ids32 + (size_t)b * SS * stride;

    const int base = tid * 16;
    int c = 0;
    #pragma unroll
    for (int i = 0; i < 16; i++)
        if (row[(base + i) * stride] == SEPTOK) c++;

    const int lane = tid & 31, w = tid >> 5;
    int incl = c;
    #pragma unroll
    for (int o = 1; o < 32; o <<= 1) {
        int t = __shfl_up_sync(0xffffffffu, incl, o);
        if (lane >= o) incl += t;
    }
    __shared__ int wsum[8], woff[8];
    if (lane == 31) wsum[w] = incl;
    __syncthreads();
    if (tid == 0) {
        int a = 0;
        #pragma unroll
        for (int i = 0; i < 8; i++) { woff[i] = a; a += wsum[i]; }
        g_nsep[b] = a;
    }
    __syncthreads();

    int off = woff[w] + incl - c;
    for (int i = 0; i < 16; i++)
        if (row[(base + i) * stride] == SEPTOK)
            g_sep_pos[b][off++] = base + i;
}

// ---------------- 2) pooling (float4, x4 unroll); emits fp16 A --------------
__global__ void pool_kernel(const float* __restrict__ hidden) {
    const int s   = blockIdx.x;   // 0..63
    const int b   = blockIdx.y;   // 0..7
    const int tid = threadIdx.x;  // 192 (= HH/4)
    const int n   = g_nsep[b];

    int t0 = 0, t1 = 0;
    if (n == 0) {
        if (s == 0) { t0 = 0; t1 = SS; }
    } else if (s < n) {
        if (s == 0) { t0 = 0; t1 = g_sep_pos[b][0] + 1; }
        else        { t0 = g_sep_pos[b][s - 1] + 1; t1 = g_sep_pos[b][s]; }
    } else if (s == n) {
        t0 = g_sep_pos[b][n - 1] + 1; t1 = SS - 1;
    }

    const float4* hb = (const float4*)(hidden + (size_t)b * SS * HH);
    float4 s0 = make_float4(0.f,0.f,0.f,0.f), s1 = s0, s2 = s0, s3 = s0;
    int t = t0;
    for (; t + 3 < t1; t += 4) {
        float4 v0 = hb[(size_t)t * 192 + tid];
        float4 v1 = hb[(size_t)(t + 1) * 192 + tid];
        float4 v2 = hb[(size_t)(t + 2) * 192 + tid];
        float4 v3 = hb[(size_t)(t + 3) * 192 + tid];
        s0.x += v0.x; s0.y += v0.y; s0.z += v0.z; s0.w += v0.w;
        s1.x += v1.x; s1.y += v1.y; s1.z += v1.z; s1.w += v1.w;
        s2.x += v2.x; s2.y += v2.y; s2.z += v2.z; s2.w += v2.w;
        s3.x += v3.x; s3.y += v3.y; s3.z += v3.z; s3.w += v3.w;
    }
    for (; t < t1; t++) {
        float4 v0 = hb[(size_t)t * 192 + tid];
        s0.x += v0.x; s0.y += v0.y; s0.z += v0.z; s0.w += v0.w;
    }
    const int cnt = t1 - t0;
    const float inv = (cnt > 0) ? (1.0f / (float)cnt) : 0.0f;
    float v[4] = { (s0.x + s1.x + s2.x + s3.x) * inv,
                   (s0.y + s1.y + s2.y + s3.y) * inv,
                   (s0.z + s1.z + s2.z + s3.z) * inv,
                   (s0.w + s1.w + s2.w + s3.w) * inv };

    const size_t rb = (size_t)(b * MS + s) * HH + tid * 4;
    *(__half2*)(&g_sentb[rb])     = __halves2half2(__float2half(v[0]), __float2half(v[1]));
    *(__half2*)(&g_sentb[rb + 2]) = __halves2half2(__float2half(v[2]), __float2half(v[3]));
}

// ---------------- 3) weight transpose, fp16 -------------------------------
// W: [K, N] row-major  ->  out: [N, K] fp16
__global__ void conv_w_kernel(const float* __restrict__ W, __half* __restrict__ out,
                              int K, int N) {
    __shared__ float t[32][33];
    const int n0 = blockIdx.x * 32, k0 = blockIdx.y * 32;
    const int tx = threadIdx.x, ty = threadIdx.y;   // 32 x 8
    #pragma unroll
    for (int i = 0; i < 4; i++)
        t[ty + i * 8][tx] = W[(size_t)(k0 + ty + i * 8) * N + n0 + tx];
    __syncthreads();
    #pragma unroll
    for (int i = 0; i < 4; i++) {
        const int nn = n0 + ty + i * 8;
        out[(size_t)nn * K + k0 + tx] = __float2half(t[tx][ty + i * 8]);
    }
}

// ---------------- 4) mma.sync fp16 GEMM, 128x128 tile, K staged 128 ---------
// A: [M, lda] K-major fp16.  B: [N, ldb] K-major fp16 (B^T).
// 3-deep cp.async ring; 8 warps 4(m)x2(n), warp tile 32x64.
// EPI==1: D + bias -> GELU -> fp16 x1.  EPI==0: fp32 split-K partials.
template<int EPI>
__global__ __launch_bounds__(256)
void mma_gemm(const __half* __restrict__ A, int lda,
              const __half* __restrict__ Bm, int ldb,
              int nStages,            // number of 128-wide K stages
              const float* __restrict__ bias,
              float* __restrict__ Cout,
              __half* __restrict__ OutB)
{
    extern __shared__ char dsm_raw[];
    char* dsm = (char*)(((uintptr_t)dsm_raw + 1023) & ~(uintptr_t)1023);

    const int tid  = threadIdx.x;
    const int wid  = tid >> 5, lane = tid & 31;
    const int m0   = blockIdx.y * 128;
    const int n0   = blockIdx.x * 128;
    const int z    = blockIdx.z;
    const int ks0  = z * nStages * 128;

    const uint32_t smBase = smem_u32(dsm);

    auto load_stage = [&](int buf, int s) {
        const int ko = ks0 + s * 128;
        const uint32_t dA = smBase + buf * 32768;
        const uint32_t dB = smBase + 98304 + buf * 32768;
        #pragma unroll
        for (int sub = 0; sub < 2; sub++) {
            const __half* Ag = A  + (size_t)m0 * lda + ko + sub * 64;
            const __half* Bg = Bm + (size_t)n0 * ldb + ko + sub * 64;
            #pragma unroll
            for (int i = 0; i < 4; i++) {
                const int ch = tid + i * 256;     // 1024 16B chunks / sub-tile
                const int r = ch >> 3, c = ch & 7;
                const uint32_t sw = sw128((uint32_t)(r * 128 + c * 16)) + sub * 16384;
                cp_async16(dA + sw, Ag + (size_t)r * lda + c * 8);
                cp_async16(dB + sw, Bg + (size_t)r * ldb + c * 8);
            }
        }
    };

    // ---- warp/lane fragment geometry
    const int wm0 = (wid & 3) * 32;
    const int wn0 = (wid >> 2) * 64;
    const int grp = lane >> 3, rowin = lane & 7;
    const int a_mloc = rowin + ((grp & 1) << 3);
    const int a_koff = (grp >> 1) << 4;
    const int b_nloc = rowin + ((grp >> 1) << 3);
    const int b_koff = (grp & 1) << 4;

    float acc[2][8][4];
    #pragma unroll
    for (int mt = 0; mt < 2; mt++)
        #pragma unroll
        for (int nt = 0; nt < 8; nt++)
            #pragma unroll
            for (int q = 0; q < 4; q++) acc[mt][nt][q] = 0.f;

    load_stage(0, 0);
    cp_commit();
    if (nStages > 1) { load_stage(1, 1); cp_commit(); }

    int buf = 0;
    for (int s = 0; s < nStages; s++) {
        if (s + 1 < nStages) cp_waitg<1>(); else cp_waitg<0>();
        __syncthreads();

        #pragma unroll
        for (int sub = 0; sub < 2; sub++) {
            const uint32_t uA = smBase + buf * 32768 + sub * 16384;
            const uint32_t uB = smBase + 98304 + buf * 32768 + sub * 16384;
            const uint32_t aRow[2] = {
                uA + (uint32_t)((wm0 + a_mloc) * 128),
                uA + (uint32_t)((wm0 + 16 + a_mloc) * 128) };
            const uint32_t aXor = (uint32_t)(((wm0 + a_mloc) & 7) << 4);
            const uint32_t bXor = (uint32_t)(((wn0 + b_nloc) & 7) << 4);

            #pragma unroll
            for (int kk = 0; kk < 4; kk++) {
                uint32_t afr[2][4];
                #pragma unroll
                for (int mt = 0; mt < 2; mt++)
                    ldsm_x4(afr[mt], aRow[mt] + (((uint32_t)(kk * 32 + a_koff)) ^ aXor));

                uint32_t bfr[8][2];
                #pragma unroll
                for (int p = 0; p < 4; p++) {
                    uint32_t r4[4];
                    const uint32_t bRow = uB + (uint32_t)((wn0 + p * 16 + b_nloc) * 128);
                    ldsm_x4(r4, bRow + (((uint32_t)(kk * 32 + b_koff)) ^ bXor));
                    bfr[2 * p][0] = r4[0]; bfr[2 * p][1] = r4[1];
                    bfr[2 * p + 1][0] = r4[2]; bfr[2 * p + 1][1] = r4[3];
                }

                #pragma unroll
                for (int mt = 0; mt < 2; mt++)
                    #pragma unroll
                    for (int nt = 0; nt < 8; nt++)
                        mma16816(acc[mt][nt], afr[mt], bfr[nt]);
            }
        }

        // 3-buffer ring: overwrite target was consumed at stage s-1; the
        // top-of-loop barrier for stage s already fenced all its readers.
        if (s + 2 < nStages) { load_stage((s + 2) % 3, s + 2); cp_commit(); }
        buf = (buf + 1) % 3;
    }

    // ---- epilogue
    #pragma unroll
    for (int mt = 0; mt < 2; mt++) {
        const int rA = m0 + wm0 + mt * 16 + (lane >> 2);
        #pragma unroll
        for (int half = 0; half < 2; half++) {
            const int r = rA + half * 8;
            if (EPI == 1) {
                const size_t rowbase = (size_t)r * F1;
                #pragma unroll
                for (int nt = 0; nt < 8; nt++) {
                    const int f = n0 + wn0 + nt * 8 + (lane & 3) * 2;
                    float v0 = gelu_exact(acc[mt][nt][2 * half]     + __ldg(&bias[f]));
                    float v1 = gelu_exact(acc[mt][nt][2 * half + 1] + __ldg(&bias[f + 1]));
                    *(__half2*)(&OutB[rowbase + f]) =
                        __halves2half2(__float2half(v0), __float2half(v1));
                }
            } else {
                float* Cp = Cout + (size_t)z * MROWS * F2 + (size_t)r * F2;
                #pragma unroll
                for (int nt = 0; nt < 8; nt++) {
                    const int f = n0 + wn0 + nt * 8 + (lane & 3) * 2;
                    float2 v; v.x = acc[mt][nt][2 * half]; v.y = acc[mt][nt][2 * half + 1];
                    *(float2*)(Cp + f) = v;
                }
            }
        }
    }
}

// ---------------- 5) fused split-K reduce + bias + GELU + head --------------
__global__ void reduce_head_kernel(const float* __restrict__ b2,
                                   const float* __restrict__ W3,
                                   const float* __restrict__ b3,
                                   float* __restrict__ out) {
    const int row = blockIdx.x;   // 512
    const int tid = threadIdx.x;  // 256
    const int idx = row * F2 + tid;
    float s = 0.f;
    #pragma unroll
    for (int i = 0; i < NSPLIT; i++) s += g_x2p[(size_t)i * MROWS * F2 + idx];
    const float x = gelu_exact(s + b2[tid]);

    __shared__ float sh0[256];
    __shared__ float sh1[256];
    sh0[tid] = x * W3[tid * 2 + 0];
    sh1[tid] = x * W3[tid * 2 + 1];
    __syncthreads();
    for (int o = 128; o > 0; o >>= 1) {
        if (tid < o) { sh0[tid] += sh0[tid + o]; sh1[tid] += sh1[tid + o]; }
        __syncthreads();
    }
    if (tid == 0) {
        out[row * 2 + 0] = sh0[0] + b3[0];
        out[row * 2 + 1] = sh1[0] + b3[1];
    }
}

// ---------------- launch ----------------------------------------------------
extern "C" void kernel_launch(void* const* d_in, const int* in_sizes, int n_in,
                              void* d_out, int out_size) {
    const float* hidden = (const float*)d_in[0];
    const int*   ids32  = (const int*)  d_in[1];
    const float* W1 = (const float*)d_in[2];
    const float* b1 = (const float*)d_in[3];
    const float* W2 = (const float*)d_in[4];
    const float* b2 = (const float*)d_in[5];
    const float* W3 = (const float*)d_in[6];
    const float* b3 = (const float*)d_in[7];
    float* out = (float*)d_out;

    void *p_sentb, *p_w1b, *p_x1b, *p_w2b, *p_x2p;
    cudaGetSymbolAddress(&p_sentb, g_sentb);
    cudaGetSymbolAddress(&p_w1b,   g_w1b);
    cudaGetSymbolAddress(&p_x1b,   g_x1b);
    cudaGetSymbolAddress(&p_w2b,   g_w2b);
    cudaGetSymbolAddress(&p_x2p,   g_x2p);

    // lazily created host-side objects (no device memory involved); the
    // enqueued work graph is identical on every call.
    static cudaStream_t s1 = nullptr;
    static cudaEvent_t eFork = nullptr, eJoin = nullptr;
    if (s1 == nullptr) {
        cudaStreamCreateWithFlags(&s1, cudaStreamNonBlocking);
        cudaEventCreateWithFlags(&eFork, cudaEventDisableTiming);
        cudaEventCreateWithFlags(&eJoin, cudaEventDisableTiming);
    }

    const int SMEM_DYN = 197632;   // 3 x (32KB A + 32KB B) + 1KB align slack
    cudaFuncSetAttribute(mma_gemm<1>, cudaFuncAttributeMaxDynamicSharedMemorySize, SMEM_DYN);
    cudaFuncSetAttribute(mma_gemm<0>, cudaFuncAttributeMaxDynamicSharedMemorySize, SMEM_DYN);

    // fork: weight conversions run on s1 concurrently with sep+pool
    cudaEventRecord(eFork, 0);
    cudaStreamWaitEvent(s1, eFork, 0);
    conv_w_kernel<<<dim3(F1 / 32, HH / 32), dim3(32, 8), 0, s1>>>(
        W1, (__half*)p_w1b, HH, F1);
    conv_w_kernel<<<dim3(F2 / 32, F1 / 32), dim3(32, 8), 0, s1>>>(
        W2, (__half*)p_w2b, F1, F2);
    cudaEventRecord(eJoin, s1);

    sep_scan_kernel<<<BB, 256>>>(ids32);
    pool_kernel<<<dim3(MS, BB), 192>>>(hidden);

    // join before GEMM1 (covers GEMM2's W2 dependency as well)
    cudaStreamWaitEvent(0, eJoin, 0);

    // GEMM1: [512, 768] x [4096, 768]^T -> gelu -> fp16 x1  (6 stages)
    mma_gemm<1><<<dim3(F1 / 128, MROWS / 128, 1), 256, SMEM_DYN>>>(
        (const __half*)p_sentb, HH, (const __half*)p_w1b, HH,
        HH / 128, b1, nullptr, (__half*)p_x1b);

    // GEMM2: [512, 4096] x [256, 4096]^T, split-K=16 -> fp32 partials (2 stages)
    mma_gemm<0><<<dim3(F2 / 128, MROWS / 128, NSPLIT), 256, SMEM_DYN>>>(
        (const __half*)p_x1b, F1, (const __half*)p_w2b, F1,
        F1 / (128 * NSPLIT), nullptr, (float*)p_x2p, nullptr);

    reduce_head_kernel<<<MROWS, 256>>>(b2, W3, b3, out);
}